// round 13
// baseline (speedup 1.0000x reference)
#include <cuda_runtime.h>
#include <cuda_bf16.h>
#include <math.h>
#include <stdint.h>

// Problem constants
#define Bv   2
#define Dv   16
#define Hv   56
#define Wv   56
#define Cv   256
#define NHv  8
#define HDv  32
#define WSv  4
#define SSv  2
#define NWIN 784
#define BWIN 1568
#define Tv   100352

// ---------------------------------------------------------------------------
// Scratch (device globals; no allocation allowed)
__device__ __nv_bfloat16 g_ln[(size_t)Tv * 256];     // ln1 out / proj out (bf16)
__device__ __nv_bfloat16 g_big[(size_t)Tv * 1024];   // qkv out (head-blocked) / fc1 out
__device__ __nv_bfloat16 g_attn[(size_t)Tv * 256];   // attn out / ln2 out
__device__ float         g_x1[(size_t)Tv * 256];     // x1 (fp32)
__device__ __nv_bfloat16 g_w[786432];
__device__ float         g_btab[8 * 8 * 64 * 64];    // [mask-type][head][i][j]

#define WOFF_QKV  0
#define WOFF_PROJ 196608
#define WOFF_FC1  262144
#define WOFF_FC2  524288
#define WTOTAL    786432

// ---------------------------------------------------------------------------
// Merged prologue: blocks [0,3072) convert weights; blocks [3072,3136) build btab.
__global__ void k_pre(const float* __restrict__ s0, const float* __restrict__ s1,
                      const float* __restrict__ s2, const float* __restrict__ s3,
                      __nv_bfloat16* __restrict__ dst,
                      const float* __restrict__ rpb, float* __restrict__ tbl) {
    if (blockIdx.x < 3072) {
        int i = blockIdx.x * 256 + threadIdx.x;
        float v;
        if (i < WOFF_PROJ)      v = s0[i - WOFF_QKV];
        else if (i < WOFF_FC1)  v = s1[i - WOFF_PROJ];
        else if (i < WOFF_FC2)  v = s2[i - WOFF_FC1];
        else                    v = s3[i - WOFF_FC2];
        dst[i] = __float2bfloat16(v);
    } else {
        int idx = blockIdx.x - 3072;       // 0..63
        int mt = idx >> 3, h = idx & 7;
        int mtd = (mt >> 2) & 1, mth = (mt >> 1) & 1, mtw = mt & 1;
        for (int e = threadIdx.x; e < 4096; e += 256) {
            int i = e >> 6, j = e & 63;
            int zi = i >> 4, yi = (i >> 2) & 3, xi = i & 3;
            int zj = j >> 4, yj = (j >> 2) & 3, xj = j & 3;
            int bi = (zi - zj + 3) * 49 + (yi - yj + 3) * 7 + (xi - xj + 3);
            float v = rpb[bi * NHv + h];
            int ld = mtd ? (zi < 2 ? 1 : 2) : 0, ldj = mtd ? (zj < 2 ? 1 : 2) : 0;
            int lh = mth ? (yi < 2 ? 1 : 2) : 0, lhj = mth ? (yj < 2 ? 1 : 2) : 0;
            int lw = mtw ? (xi < 2 ? 1 : 2) : 0, lwj = mtw ? (xj < 2 ? 1 : 2) : 0;
            if (ld != ldj || lh != lhj || lw != lwj) v -= 100.0f;
            tbl[((mt * 8 + h) << 12) + e] = v;
        }
    }
}

// ---------------------------------------------------------------------------
// Warp-wide LN helpers
__device__ __forceinline__ void warp_ln8(const float* vin, float* vout,
                                         const float* __restrict__ g,
                                         const float* __restrict__ b, int cbase) {
    float s1 = 0.f, s2 = 0.f;
    #pragma unroll
    for (int t = 0; t < 8; t++) { s1 += vin[t]; s2 += vin[t] * vin[t]; }
    #pragma unroll
    for (int o = 16; o > 0; o >>= 1) {
        s1 += __shfl_xor_sync(0xffffffffu, s1, o);
        s2 += __shfl_xor_sync(0xffffffffu, s2, o);
    }
    float mu = s1 * (1.0f / 256.0f);
    float var = s2 * (1.0f / 256.0f) - mu * mu;
    float inv = rsqrtf(var + 1e-5f);
    float4 g0 = *(const float4*)(g + cbase);
    float4 g1 = *(const float4*)(g + cbase + 4);
    float4 b0 = *(const float4*)(b + cbase);
    float4 b1 = *(const float4*)(b + cbase + 4);
    vout[0] = (vin[0] - mu) * inv * g0.x + b0.x;
    vout[1] = (vin[1] - mu) * inv * g0.y + b0.y;
    vout[2] = (vin[2] - mu) * inv * g0.z + b0.z;
    vout[3] = (vin[3] - mu) * inv * g0.w + b0.w;
    vout[4] = (vin[4] - mu) * inv * g1.x + b1.x;
    vout[5] = (vin[5] - mu) * inv * g1.y + b1.y;
    vout[6] = (vin[6] - mu) * inv * g1.z + b1.z;
    vout[7] = (vin[7] - mu) * inv * g1.w + b1.w;
}

__device__ __forceinline__ uint4 pack8_bf16(const float* v) {
    uint4 r;
    __nv_bfloat162 p0 = __floats2bfloat162_rn(v[0], v[1]);
    __nv_bfloat162 p1 = __floats2bfloat162_rn(v[2], v[3]);
    __nv_bfloat162 p2 = __floats2bfloat162_rn(v[4], v[5]);
    __nv_bfloat162 p3 = __floats2bfloat162_rn(v[6], v[7]);
    r.x = *(uint32_t*)&p0; r.y = *(uint32_t*)&p1;
    r.z = *(uint32_t*)&p2; r.w = *(uint32_t*)&p3;
    return r;
}

__global__ void __launch_bounds__(256) k_ln1_v2(
    const float* __restrict__ x, const float* __restrict__ g,
    const float* __restrict__ bta, __nv_bfloat16* __restrict__ out) {
    int wt = blockIdx.x * 8 + (threadIdx.x >> 5);
    int lane = threadIdx.x & 31;
    int i  = wt & 63, b_ = wt >> 6;
    int b = b_ / NWIN, widx = b_ % NWIN;
    int wd = widx / 196, r = widx % 196, wh = r / 14, ww = r % 14;
    int zi = i >> 4, yi = (i >> 2) & 3, xi = i & 3;
    int d = (wd * 4 + zi + SSv) & 15;
    int h = wh * 4 + yi + SSv; if (h >= Hv) h -= Hv;
    int w = ww * 4 + xi + SSv; if (w >= Wv) w -= Wv;
    const float* row = x + ((size_t)((b * Dv + d) * Hv + h) * Wv + w) * Cv + lane * 8;
    float vin[8], vo[8];
    *(float4*)vin     = *(const float4*)row;
    *(float4*)(vin+4) = *(const float4*)(row + 4);
    warp_ln8(vin, vo, g, bta, lane * 8);
    *(uint4*)(out + (size_t)wt * Cv + lane * 8) = pack8_bf16(vo);
}

// x1 = x + reverse(roll(proj_out bf16));  LN2 -> lnout bf16
__global__ void __launch_bounds__(256) k_x1_ln2_v2(
    const float* __restrict__ x, const __nv_bfloat16* __restrict__ projout,
    const float* __restrict__ g, const float* __restrict__ bta,
    float* __restrict__ x1, __nv_bfloat16* __restrict__ lnout) {
    int t = blockIdx.x * 8 + (threadIdx.x >> 5);
    int lane = threadIdx.x & 31;
    int w = t % Wv, tmp = t / Wv;
    int h = tmp % Hv; tmp /= Hv;
    int d = tmp % Dv; int b = tmp / Dv;
    int ds = (d - SSv) & 15;
    int hs = h - SSv; if (hs < 0) hs += Hv;
    int ws = w - SSv; if (ws < 0) ws += Wv;
    int wt = ((b * NWIN + (ds >> 2) * 196 + (hs >> 2) * 14 + (ws >> 2)) << 6)
             + ((ds & 3) << 4) + ((hs & 3) << 2) + (ws & 3);
    const float* xr = x + (size_t)t * Cv + lane * 8;
    uint4 pv = *(const uint4*)(projout + (size_t)wt * Cv + lane * 8);
    __nv_bfloat162 p0 = *(__nv_bfloat162*)&pv.x;
    __nv_bfloat162 p1 = *(__nv_bfloat162*)&pv.y;
    __nv_bfloat162 p2 = *(__nv_bfloat162*)&pv.z;
    __nv_bfloat162 p3 = *(__nv_bfloat162*)&pv.w;
    float4 a0 = *(const float4*)xr;
    float4 a1 = *(const float4*)(xr + 4);
    float vin[8], vo[8];
    vin[0] = a0.x + __bfloat162float(p0.x); vin[1] = a0.y + __bfloat162float(p0.y);
    vin[2] = a0.z + __bfloat162float(p1.x); vin[3] = a0.w + __bfloat162float(p1.y);
    vin[4] = a1.x + __bfloat162float(p2.x); vin[5] = a1.y + __bfloat162float(p2.y);
    vin[6] = a1.z + __bfloat162float(p3.x); vin[7] = a1.w + __bfloat162float(p3.y);
    float* x1r = x1 + (size_t)t * Cv + lane * 8;
    *(float4*)x1r       = *(float4*)vin;
    *(float4*)(x1r + 4) = *(float4*)(vin + 4);
    warp_ln8(vin, vo, g, bta, lane * 8);
    *(uint4*)(lnout + (size_t)t * Cv + lane * 8) = pack8_bf16(vo);
}

// ---------------------------------------------------------------------------
// MMA primitives
__device__ __forceinline__ void ldsm_x4(uint32_t& r0, uint32_t& r1, uint32_t& r2, uint32_t& r3,
                                        uint32_t addr) {
    asm volatile("ldmatrix.sync.aligned.m8n8.x4.shared.b16 {%0,%1,%2,%3}, [%4];\n"
                 : "=r"(r0), "=r"(r1), "=r"(r2), "=r"(r3) : "r"(addr));
}
__device__ __forceinline__ void ldsm_x4t(uint32_t& r0, uint32_t& r1, uint32_t& r2, uint32_t& r3,
                                         uint32_t addr) {
    asm volatile("ldmatrix.sync.aligned.m8n8.x4.trans.shared.b16 {%0,%1,%2,%3}, [%4];\n"
                 : "=r"(r0), "=r"(r1), "=r"(r2), "=r"(r3) : "r"(addr));
}
__device__ __forceinline__ void mma_bf16(float& d0, float& d1, float& d2, float& d3,
                                         uint32_t a0, uint32_t a1, uint32_t a2, uint32_t a3,
                                         uint32_t b0, uint32_t b1) {
    asm volatile("mma.sync.aligned.m16n8k16.row.col.f32.bf16.bf16.f32 "
                 "{%0,%1,%2,%3}, {%4,%5,%6,%7}, {%8,%9}, {%0,%1,%2,%3};\n"
                 : "+f"(d0), "+f"(d1), "+f"(d2), "+f"(d3)
                 : "r"(a0), "r"(a1), "r"(a2), "r"(a3), "r"(b0), "r"(b1));
}
__device__ __forceinline__ void cp16(uint32_t dst, const void* src) {
    asm volatile("cp.async.cg.shared.global [%0], [%1], 16;\n" :: "r"(dst), "l"(src));
}

extern __shared__ char dyn_smem[];

// ---------------------------------------------------------------------------
// K3: tensor-core windowed attention; qkv is head-blocked (R11 proven).
#define ATT_STRIDE 40
#define ATT_MAT    (64 * ATT_STRIDE)
#define ATT_SMEM   (3 * 4 * ATT_MAT * 2)

__global__ void __launch_bounds__(256, 2) k_attn_mma(
    const __nv_bfloat16* __restrict__ qkv, const float* __restrict__ btab,
    __nv_bfloat16* __restrict__ out) {
    int wnd  = blockIdx.x >> 1;
    int half = blockIdx.x & 1;
    int tid  = threadIdx.x;
    int lane = tid & 31;
    int warp = tid >> 5;
    int hl   = warp >> 1;
    int sub  = warp & 1;
    int head = half * 4 + hl;

    __nv_bfloat16* smQ = (__nv_bfloat16*)dyn_smem;
    __nv_bfloat16* smK = smQ + 4 * ATT_MAT;
    __nv_bfloat16* smV = smK + 4 * ATT_MAT;

    uint32_t sq = (uint32_t)__cvta_generic_to_shared(smQ + hl * ATT_MAT);
    uint32_t sk = (uint32_t)__cvta_generic_to_shared(smK + hl * ATT_MAT);
    uint32_t sv = (uint32_t)__cvta_generic_to_shared(smV + hl * ATT_MAT);

    const __nv_bfloat16* qb = qkv + (((size_t)wnd * 24 +  0 + head) << 11);
    const __nv_bfloat16* kb = qkv + (((size_t)wnd * 24 +  8 + head) << 11);
    const __nv_bfloat16* vb = qkv + (((size_t)wnd * 24 + 16 + head) << 11);
    #pragma unroll
    for (int c = 0; c < 4; c++) {
        int chunk = c * 64 + sub * 32 + lane;
        int row = chunk >> 2, grp = (chunk & 3) * 8;
        uint32_t off = (uint32_t)(row * ATT_STRIDE + grp) * 2;
        cp16(sq + off, qb + chunk * 8);
        cp16(sk + off, kb + chunk * 8);
        cp16(sv + off, vb + chunk * 8);
    }
    asm volatile("cp.async.commit_group;\n" ::: "memory");

    int widx = wnd % NWIN;
    int wd = widx / 196, rr = widx % 196, wh = rr / 14, ww = rr % 14;
    int mt = ((wd == 3) << 2) | ((wh == 13) << 1) | (ww == 13);
    const float* tb = btab + (((size_t)mt * 8 + head) << 12);

    asm volatile("cp.async.wait_group 0;\n" ::: "memory");
    __syncthreads();

    float acc[2][8][4];
    #pragma unroll
    for (int a = 0; a < 2; a++)
        #pragma unroll
        for (int bq = 0; bq < 8; bq++)
            #pragma unroll
            for (int t = 0; t < 4; t++) acc[a][bq][t] = 0.f;

    int arow = lane & 15;
    int asel = (lane >> 4) << 3;
    int br   = (lane & 7) + ((lane >> 4) << 3);
    int bkh  = ((lane >> 3) & 1) << 3;
    int m0   = sub * 32;

    #pragma unroll
    for (int ks = 0; ks < 2; ks++) {
        int k0 = ks * 16;
        uint32_t af[2][4];
        #pragma unroll
        for (int mi = 0; mi < 2; mi++)
            ldsm_x4(af[mi][0], af[mi][1], af[mi][2], af[mi][3],
                    sq + (uint32_t)((m0 + mi * 16 + arow) * ATT_STRIDE + k0 + asel) * 2);
        uint32_t bf[8][2];
        #pragma unroll
        for (int nb = 0; nb < 4; nb++)
            ldsm_x4(bf[2*nb][0], bf[2*nb][1], bf[2*nb+1][0], bf[2*nb+1][1],
                    sk + (uint32_t)((nb * 16 + br) * ATT_STRIDE + k0 + bkh) * 2);
        #pragma unroll
        for (int mi = 0; mi < 2; mi++)
            #pragma unroll
            for (int nj = 0; nj < 8; nj++)
                mma_bf16(acc[mi][nj][0], acc[mi][nj][1], acc[mi][nj][2], acc[mi][nj][3],
                         af[mi][0], af[mi][1], af[mi][2], af[mi][3], bf[nj][0], bf[nj][1]);
    }

    int r0 = lane >> 2;
    int cq = (lane & 3) * 2;

    const float scale = 0.17677669529663689f;
    #pragma unroll
    for (int mi = 0; mi < 2; mi++)
        #pragma unroll
        for (int hh = 0; hh < 2; hh++) {
            int i = m0 + mi * 16 + hh * 8 + r0;
            const float* tr = tb + i * 64 + cq;
            #pragma unroll
            for (int nj = 0; nj < 8; nj++) {
                float2 bv = __ldg((const float2*)(tr + nj * 8));
                acc[mi][nj][hh * 2 + 0] = acc[mi][nj][hh * 2 + 0] * scale + bv.x;
                acc[mi][nj][hh * 2 + 1] = acc[mi][nj][hh * 2 + 1] * scale + bv.y;
            }
        }

    float invs[2][2];
    #pragma unroll
    for (int mi = 0; mi < 2; mi++)
        #pragma unroll
        for (int hh = 0; hh < 2; hh++) {
            float m = -1e30f;
            #pragma unroll
            for (int nj = 0; nj < 8; nj++) {
                m = fmaxf(m, acc[mi][nj][hh * 2]);
                m = fmaxf(m, acc[mi][nj][hh * 2 + 1]);
            }
            m = fmaxf(m, __shfl_xor_sync(0xffffffffu, m, 1));
            m = fmaxf(m, __shfl_xor_sync(0xffffffffu, m, 2));
            float sum = 0.f;
            #pragma unroll
            for (int nj = 0; nj < 8; nj++) {
                float e0 = __expf(acc[mi][nj][hh * 2]     - m);
                float e1 = __expf(acc[mi][nj][hh * 2 + 1] - m);
                acc[mi][nj][hh * 2] = e0; acc[mi][nj][hh * 2 + 1] = e1;
                sum += e0 + e1;
            }
            sum += __shfl_xor_sync(0xffffffffu, sum, 1);
            sum += __shfl_xor_sync(0xffffffffu, sum, 2);
            invs[mi][hh] = 1.0f / sum;
        }

    uint32_t pk[2][8][2];
    #pragma unroll
    for (int mi = 0; mi < 2; mi++)
        #pragma unroll
        for (int t = 0; t < 8; t++) {
            __nv_bfloat162 p0 = __floats2bfloat162_rn(acc[mi][t][0] * invs[mi][0],
                                                      acc[mi][t][1] * invs[mi][0]);
            __nv_bfloat162 p1 = __floats2bfloat162_rn(acc[mi][t][2] * invs[mi][1],
                                                      acc[mi][t][3] * invs[mi][1]);
            pk[mi][t][0] = *(uint32_t*)&p0;
            pk[mi][t][1] = *(uint32_t*)&p1;
        }

    float o[2][4][4];
    #pragma unroll
    for (int a = 0; a < 2; a++)
        #pragma unroll
        for (int bq = 0; bq < 4; bq++)
            #pragma unroll
            for (int t = 0; t < 4; t++) o[a][bq][t] = 0.f;

    #pragma unroll
    for (int kt = 0; kt < 4; kt++) {
        uint32_t bv[4][2];
        #pragma unroll
        for (int nb = 0; nb < 2; nb++)
            ldsm_x4t(bv[2*nb][0], bv[2*nb][1], bv[2*nb+1][0], bv[2*nb+1][1],
                     sv + (uint32_t)((kt * 16 + arow) * ATT_STRIDE + nb * 16 + asel) * 2);
        #pragma unroll
        for (int mi = 0; mi < 2; mi++)
            #pragma unroll
            for (int nt = 0; nt < 4; nt++)
                mma_bf16(o[mi][nt][0], o[mi][nt][1], o[mi][nt][2], o[mi][nt][3],
                         pk[mi][2*kt][0], pk[mi][2*kt][1], pk[mi][2*kt+1][0], pk[mi][2*kt+1][1],
                         bv[nt][0], bv[nt][1]);
    }

    #pragma unroll
    for (int mi = 0; mi < 2; mi++)
        #pragma unroll
        for (int nt = 0; nt < 4; nt++)
            #pragma unroll
            for (int hh = 0; hh < 2; hh++) {
                int row = m0 + mi * 16 + hh * 8 + r0;
                int col = head * HDv + nt * 8 + cq;
                __nv_bfloat162 p = __floats2bfloat162_rn(o[mi][nt][hh * 2],
                                                         o[mi][nt][hh * 2 + 1]);
                *(__nv_bfloat162*)(out + ((size_t)wnd * 64 + row) * Cv + col) = p;
            }
}

// ---------------------------------------------------------------------------
// High-occupancy bf16 GEMM: 256 threads, 8 warps (4x2) of 32x32 warp tiles,
// CTA 128x64, BK=64, 2-stage cp.async ring, 3 CTAs/SM (24 warps).
// EPI: 0 = bf16 out, 2 = GELU + bf16 out, 3 = +res fp32 out, 4 = head-blocked bf16
#define S2_STRIDE 72
#define S2A (128 * S2_STRIDE * 2)     // 18432 B
#define S2B (64 * S2_STRIDE * 2)      //  9216 B
#define G2_SMEM (2 * (S2A + S2B))     // 55296 B

template<int EPI, int KN>
__global__ void __launch_bounds__(256, 3) k_mmagemm32(
    const __nv_bfloat16* __restrict__ A, const __nv_bfloat16* __restrict__ Bw,
    const float* __restrict__ bias, void* __restrict__ Cout,
    int N, const float* __restrict__ res) {
    constexpr int K = KN;
    constexpr int NIT = K >> 6;
    int tid  = threadIdx.x;
    int lane = tid & 31, warp = tid >> 5;
    int wy = warp >> 1, wx = warp & 1;       // 4 x 2 warps of 32x32
    int rowBase = blockIdx.y * 128;
    int colBase = blockIdx.x * 64;

    uint32_t sbase = (uint32_t)__cvta_generic_to_shared(dyn_smem);
    uint32_t sAs[2], sBs[2];
    #pragma unroll
    for (int s = 0; s < 2; s++) {
        sAs[s] = sbase + s * (S2A + S2B);
        sBs[s] = sAs[s] + S2A;
    }

    auto issue = [&](int it) {
        int slot = it & 1;
        int k0 = it << 6;
        uint32_t sAu = sAs[slot], sBu = sBs[slot];
        #pragma unroll
        for (int i = 0; i < 4; i++) {            // A: 128x64 = 1024 chunks
            int ch = tid + i * 256;
            int ar = ch >> 3, ac = ch & 7;
            cp16(sAu + (uint32_t)(ar * S2_STRIDE + ac * 8) * 2,
                 A + (size_t)(rowBase + ar) * K + k0 + ac * 8);
        }
        #pragma unroll
        for (int i = 0; i < 2; i++) {            // B: 64x64 = 512 chunks
            int ch = tid + i * 256;
            int bk = ch >> 3, bn = ch & 7;
            cp16(sBu + (uint32_t)(bk * S2_STRIDE + bn * 8) * 2,
                 Bw + (size_t)(k0 + bk) * N + colBase + bn * 8);
        }
        asm volatile("cp.async.commit_group;\n" ::: "memory");
    };

    issue(0);
    if (NIT > 1) issue(1);

    float acc[2][4][4];
    #pragma unroll
    for (int i = 0; i < 2; i++)
        #pragma unroll
        for (int j = 0; j < 4; j++)
            #pragma unroll
            for (int t = 0; t < 4; t++) acc[i][j][t] = 0.f;

    int m0  = wy * 32;
    int n0w = wx * 32;
    int arow = lane & 15;
    int asel = (lane >> 4) << 3;
    int ksrot = warp & 3;

    for (int it = 0; it < NIT; it++) {
        if (it + 1 < NIT) asm volatile("cp.async.wait_group 1;\n" ::: "memory");
        else              asm volatile("cp.async.wait_group 0;\n" ::: "memory");
        __syncthreads();

        int slot = it & 1;
        uint32_t sAu = sAs[slot], sBu = sBs[slot];

        #pragma unroll
        for (int ksi = 0; ksi < 4; ksi++) {
            int ks = (ksi + ksrot) & 3;
            int k0 = ks * 16;
            uint32_t a[2][4];
            #pragma unroll
            for (int mi = 0; mi < 2; mi++)
                ldsm_x4(a[mi][0], a[mi][1], a[mi][2], a[mi][3],
                        sAu + (uint32_t)((m0 + mi * 16 + arow) * S2_STRIDE + k0 + asel) * 2);
            uint32_t b[4][2];
            #pragma unroll
            for (int nb = 0; nb < 2; nb++)
                ldsm_x4t(b[2 * nb][0], b[2 * nb][1], b[2 * nb + 1][0], b[2 * nb + 1][1],
                         sBu + (uint32_t)((k0 + (lane & 15)) * S2_STRIDE
                                          + n0w + nb * 16 + ((lane >> 4) << 3)) * 2);
            #pragma unroll
            for (int mi = 0; mi < 2; mi++)
                #pragma unroll
                for (int ni = 0; ni < 4; ni++)
                    mma_bf16(acc[mi][ni][0], acc[mi][ni][1], acc[mi][ni][2], acc[mi][ni][3],
                             a[mi][0], a[mi][1], a[mi][2], a[mi][3], b[ni][0], b[ni][1]);
        }
        __syncthreads();
        if (it + 2 < NIT) issue(it + 2);
    }

    int gr = lane >> 2, gc = (lane & 3) * 2;
    float bias_r[4][2];
    #pragma unroll
    for (int ni = 0; ni < 4; ni++) {
        int col = colBase + n0w + ni * 8 + gc;
        bias_r[ni][0] = bias[col];
        bias_r[ni][1] = bias[col + 1];
    }
    #pragma unroll
    for (int mi = 0; mi < 2; mi++) {
        #pragma unroll
        for (int ni = 0; ni < 4; ni++) {
            int col = colBase + n0w + ni * 8 + gc;
            #pragma unroll
            for (int half = 0; half < 2; half++) {
                size_t row = (size_t)(rowBase + m0 + mi * 16 + gr + half * 8);
                float v0 = acc[mi][ni][half * 2 + 0] + bias_r[ni][0];
                float v1 = acc[mi][ni][half * 2 + 1] + bias_r[ni][1];
                if (EPI == 2) {
                    v0 = 0.5f * v0 * (1.0f + erff(v0 * 0.70710678118654752f));
                    v1 = 0.5f * v1 * (1.0f + erff(v1 * 0.70710678118654752f));
                }
                if (EPI == 3) {
                    v0 += res[row * N + col];
                    v1 += res[row * N + col + 1];
                    float2* p = (float2*)((float*)Cout + row * N + col);
                    *p = make_float2(v0, v1);
                } else if (EPI == 4) {
                    size_t addr = ((((row >> 6) * 24) + (size_t)(col >> 5)) << 11)
                                  + ((row & 63) << 5) + (col & 31);
                    *(__nv_bfloat162*)((__nv_bfloat16*)Cout + addr) =
                        __floats2bfloat162_rn(v0, v1);
                } else {
                    __nv_bfloat162* p = (__nv_bfloat162*)((__nv_bfloat16*)Cout + row * N + col);
                    *p = __floats2bfloat162_rn(v0, v1);
                }
            }
        }
    }
}

// ---------------------------------------------------------------------------
extern "C" void kernel_launch(void* const* d_in, const int* in_sizes, int n_in,
                              void* d_out, int out_size) {
    const float* x      = (const float*)d_in[0];
    const float* n1g    = (const float*)d_in[1];
    const float* n1b    = (const float*)d_in[2];
    const float* qkv_w  = (const float*)d_in[3];
    const float* qkv_b  = (const float*)d_in[4];
    const float* proj_w = (const float*)d_in[5];
    const float* proj_b = (const float*)d_in[6];
    const float* rpb    = (const float*)d_in[7];
    const float* n2g    = (const float*)d_in[8];
    const float* n2b    = (const float*)d_in[9];
    const float* fc1_w  = (const float*)d_in[10];
    const float* fc1_b  = (const float*)d_in[11];
    const float* fc2_w  = (const float*)d_in[12];
    const float* fc2_b  = (const float*)d_in[13];
    float* out = (float*)d_out;

    __nv_bfloat16 *ln, *big, *attn, *wts;
    float *x1, *btab;
    cudaGetSymbolAddress((void**)&ln,   g_ln);
    cudaGetSymbolAddress((void**)&big,  g_big);
    cudaGetSymbolAddress((void**)&attn, g_attn);
    cudaGetSymbolAddress((void**)&x1,   g_x1);
    cudaGetSymbolAddress((void**)&wts,  g_w);
    cudaGetSymbolAddress((void**)&btab, g_btab);

    cudaFuncSetAttribute(k_attn_mma, cudaFuncAttributeMaxDynamicSharedMemorySize, ATT_SMEM);
    cudaFuncSetAttribute((const void*)k_mmagemm32<4, 256>,  cudaFuncAttributeMaxDynamicSharedMemorySize, G2_SMEM);
    cudaFuncSetAttribute((const void*)k_mmagemm32<0, 256>,  cudaFuncAttributeMaxDynamicSharedMemorySize, G2_SMEM);
    cudaFuncSetAttribute((const void*)k_mmagemm32<2, 256>,  cudaFuncAttributeMaxDynamicSharedMemorySize, G2_SMEM);
    cudaFuncSetAttribute((const void*)k_mmagemm32<3, 1024>, cudaFuncAttributeMaxDynamicSharedMemorySize, G2_SMEM);

    // 0) merged prologue: weights -> bf16, bias+mask table
    k_pre<<<3136, 256>>>(qkv_w, proj_w, fc1_w, fc2_w, wts, rpb, btab);

    // 1) LN1 + roll + window partition -> ln
    k_ln1_v2<<<Tv / 8, 256>>>(x, n1g, n1b, ln);
    // 2) qkv GEMM: ln -> big (head-blocked layout)
    k_mmagemm32<4, 256><<<dim3(768 / 64, Tv / 128), 256, G2_SMEM>>>(ln, wts + WOFF_QKV, qkv_b, big, 768, nullptr);
    // 3) attention: big (head-blocked) -> attn
    k_attn_mma<<<BWIN * 2, 256, ATT_SMEM>>>(big, btab, attn);
    // 4) proj GEMM: attn -> ln (bf16)
    k_mmagemm32<0, 256><<<dim3(256 / 64, Tv / 128), 256, G2_SMEM>>>(attn, wts + WOFF_PROJ, proj_b, ln, 256, nullptr);
    // 5) x1 = x + reverse(roll(ln)); LN2 -> x1 (fp32), attn (bf16)
    k_x1_ln2_v2<<<Tv / 8, 256>>>(x, ln, n2g, n2b, x1, attn);
    // 6) fc1 + GELU: attn -> big
    k_mmagemm32<2, 256><<<dim3(1024 / 64, Tv / 128), 256, G2_SMEM>>>(attn, wts + WOFF_FC1, fc1_b, big, 1024, nullptr);
    // 7) fc2 + residual(x1): big -> out
    k_mmagemm32<3, 1024><<<dim3(256 / 64, Tv / 128), 256, G2_SMEM>>>(big, wts + WOFF_FC2, fc2_b, out, 256, x1);
}

// round 14
// speedup vs baseline: 1.0540x; 1.0540x over previous
#include <cuda_runtime.h>
#include <cuda_bf16.h>
#include <math.h>
#include <stdint.h>

// Problem constants
#define Bv   2
#define Dv   16
#define Hv   56
#define Wv   56
#define Cv   256
#define NHv  8
#define HDv  32
#define WSv  4
#define SSv  2
#define NWIN 784
#define BWIN 1568
#define Tv   100352

// ---------------------------------------------------------------------------
// Scratch (device globals; no allocation allowed)
__device__ __nv_bfloat16 g_ln[(size_t)Tv * 256];     // ln1 out / proj out (bf16)
__device__ __nv_bfloat16 g_big[(size_t)Tv * 1024];   // qkv out (head-blocked) / fc1 out
__device__ __nv_bfloat16 g_attn[(size_t)Tv * 256];   // attn out (head-blocked) / ln2 out
__device__ float         g_x1[(size_t)Tv * 256];     // x1 (fp32)
__device__ __nv_bfloat16 g_w[786432];
__device__ float         g_btab[8 * 8 * 64 * 64];    // [mask-type][head][i][j]

#define WOFF_QKV  0
#define WOFF_PROJ 196608
#define WOFF_FC1  262144
#define WOFF_FC2  524288
#define WTOTAL    786432

// ---------------------------------------------------------------------------
// Merged prologue: blocks [0,3072) convert weights; blocks [3072,3136) build btab.
__global__ void k_pre(const float* __restrict__ s0, const float* __restrict__ s1,
                      const float* __restrict__ s2, const float* __restrict__ s3,
                      __nv_bfloat16* __restrict__ dst,
                      const float* __restrict__ rpb, float* __restrict__ tbl) {
    if (blockIdx.x < 3072) {
        int i = blockIdx.x * 256 + threadIdx.x;
        float v;
        if (i < WOFF_PROJ)      v = s0[i - WOFF_QKV];
        else if (i < WOFF_FC1)  v = s1[i - WOFF_PROJ];
        else if (i < WOFF_FC2)  v = s2[i - WOFF_FC1];
        else                    v = s3[i - WOFF_FC2];
        dst[i] = __float2bfloat16(v);
    } else {
        int idx = blockIdx.x - 3072;       // 0..63
        int mt = idx >> 3, h = idx & 7;
        int mtd = (mt >> 2) & 1, mth = (mt >> 1) & 1, mtw = mt & 1;
        for (int e = threadIdx.x; e < 4096; e += 256) {
            int i = e >> 6, j = e & 63;
            int zi = i >> 4, yi = (i >> 2) & 3, xi = i & 3;
            int zj = j >> 4, yj = (j >> 2) & 3, xj = j & 3;
            int bi = (zi - zj + 3) * 49 + (yi - yj + 3) * 7 + (xi - xj + 3);
            float v = rpb[bi * NHv + h];
            int ld = mtd ? (zi < 2 ? 1 : 2) : 0, ldj = mtd ? (zj < 2 ? 1 : 2) : 0;
            int lh = mth ? (yi < 2 ? 1 : 2) : 0, lhj = mth ? (yj < 2 ? 1 : 2) : 0;
            int lw = mtw ? (xi < 2 ? 1 : 2) : 0, lwj = mtw ? (xj < 2 ? 1 : 2) : 0;
            if (ld != ldj || lh != lhj || lw != lwj) v -= 100.0f;
            tbl[((mt * 8 + h) << 12) + e] = v;
        }
    }
}

// ---------------------------------------------------------------------------
// Warp-wide LN helpers
__device__ __forceinline__ void warp_ln8(const float* vin, float* vout,
                                         const float* __restrict__ g,
                                         const float* __restrict__ b, int cbase) {
    float s1 = 0.f, s2 = 0.f;
    #pragma unroll
    for (int t = 0; t < 8; t++) { s1 += vin[t]; s2 += vin[t] * vin[t]; }
    #pragma unroll
    for (int o = 16; o > 0; o >>= 1) {
        s1 += __shfl_xor_sync(0xffffffffu, s1, o);
        s2 += __shfl_xor_sync(0xffffffffu, s2, o);
    }
    float mu = s1 * (1.0f / 256.0f);
    float var = s2 * (1.0f / 256.0f) - mu * mu;
    float inv = rsqrtf(var + 1e-5f);
    float4 g0 = *(const float4*)(g + cbase);
    float4 g1 = *(const float4*)(g + cbase + 4);
    float4 b0 = *(const float4*)(b + cbase);
    float4 b1 = *(const float4*)(b + cbase + 4);
    vout[0] = (vin[0] - mu) * inv * g0.x + b0.x;
    vout[1] = (vin[1] - mu) * inv * g0.y + b0.y;
    vout[2] = (vin[2] - mu) * inv * g0.z + b0.z;
    vout[3] = (vin[3] - mu) * inv * g0.w + b0.w;
    vout[4] = (vin[4] - mu) * inv * g1.x + b1.x;
    vout[5] = (vin[5] - mu) * inv * g1.y + b1.y;
    vout[6] = (vin[6] - mu) * inv * g1.z + b1.z;
    vout[7] = (vin[7] - mu) * inv * g1.w + b1.w;
}

__device__ __forceinline__ uint4 pack8_bf16(const float* v) {
    uint4 r;
    __nv_bfloat162 p0 = __floats2bfloat162_rn(v[0], v[1]);
    __nv_bfloat162 p1 = __floats2bfloat162_rn(v[2], v[3]);
    __nv_bfloat162 p2 = __floats2bfloat162_rn(v[4], v[5]);
    __nv_bfloat162 p3 = __floats2bfloat162_rn(v[6], v[7]);
    r.x = *(uint32_t*)&p0; r.y = *(uint32_t*)&p1;
    r.z = *(uint32_t*)&p2; r.w = *(uint32_t*)&p3;
    return r;
}

__global__ void __launch_bounds__(256) k_ln1_v2(
    const float* __restrict__ x, const float* __restrict__ g,
    const float* __restrict__ bta, __nv_bfloat16* __restrict__ out) {
    int wt = blockIdx.x * 8 + (threadIdx.x >> 5);
    int lane = threadIdx.x & 31;
    int i  = wt & 63, b_ = wt >> 6;
    int b = b_ / NWIN, widx = b_ % NWIN;
    int wd = widx / 196, r = widx % 196, wh = r / 14, ww = r % 14;
    int zi = i >> 4, yi = (i >> 2) & 3, xi = i & 3;
    int d = (wd * 4 + zi + SSv) & 15;
    int h = wh * 4 + yi + SSv; if (h >= Hv) h -= Hv;
    int w = ww * 4 + xi + SSv; if (w >= Wv) w -= Wv;
    const float* row = x + ((size_t)((b * Dv + d) * Hv + h) * Wv + w) * Cv + lane * 8;
    float vin[8], vo[8];
    *(float4*)vin     = *(const float4*)row;
    *(float4*)(vin+4) = *(const float4*)(row + 4);
    warp_ln8(vin, vo, g, bta, lane * 8);
    *(uint4*)(out + (size_t)wt * Cv + lane * 8) = pack8_bf16(vo);
}

// x1 = x + reverse(roll(proj_out bf16));  LN2 -> lnout bf16
__global__ void __launch_bounds__(256) k_x1_ln2_v2(
    const float* __restrict__ x, const __nv_bfloat16* __restrict__ projout,
    const float* __restrict__ g, const float* __restrict__ bta,
    float* __restrict__ x1, __nv_bfloat16* __restrict__ lnout) {
    int t = blockIdx.x * 8 + (threadIdx.x >> 5);
    int lane = threadIdx.x & 31;
    int w = t % Wv, tmp = t / Wv;
    int h = tmp % Hv; tmp /= Hv;
    int d = tmp % Dv; int b = tmp / Dv;
    int ds = (d - SSv) & 15;
    int hs = h - SSv; if (hs < 0) hs += Hv;
    int ws = w - SSv; if (ws < 0) ws += Wv;
    int wt = ((b * NWIN + (ds >> 2) * 196 + (hs >> 2) * 14 + (ws >> 2)) << 6)
             + ((ds & 3) << 4) + ((hs & 3) << 2) + (ws & 3);
    const float* xr = x + (size_t)t * Cv + lane * 8;
    uint4 pv = *(const uint4*)(projout + (size_t)wt * Cv + lane * 8);
    __nv_bfloat162 p0 = *(__nv_bfloat162*)&pv.x;
    __nv_bfloat162 p1 = *(__nv_bfloat162*)&pv.y;
    __nv_bfloat162 p2 = *(__nv_bfloat162*)&pv.z;
    __nv_bfloat162 p3 = *(__nv_bfloat162*)&pv.w;
    float4 a0 = *(const float4*)xr;
    float4 a1 = *(const float4*)(xr + 4);
    float vin[8], vo[8];
    vin[0] = a0.x + __bfloat162float(p0.x); vin[1] = a0.y + __bfloat162float(p0.y);
    vin[2] = a0.z + __bfloat162float(p1.x); vin[3] = a0.w + __bfloat162float(p1.y);
    vin[4] = a1.x + __bfloat162float(p2.x); vin[5] = a1.y + __bfloat162float(p2.y);
    vin[6] = a1.z + __bfloat162float(p3.x); vin[7] = a1.w + __bfloat162float(p3.y);
    float* x1r = x1 + (size_t)t * Cv + lane * 8;
    *(float4*)x1r       = *(float4*)vin;
    *(float4*)(x1r + 4) = *(float4*)(vin + 4);
    warp_ln8(vin, vo, g, bta, lane * 8);
    *(uint4*)(lnout + (size_t)t * Cv + lane * 8) = pack8_bf16(vo);
}

// ---------------------------------------------------------------------------
// MMA primitives
__device__ __forceinline__ void ldsm_x4(uint32_t& r0, uint32_t& r1, uint32_t& r2, uint32_t& r3,
                                        uint32_t addr) {
    asm volatile("ldmatrix.sync.aligned.m8n8.x4.shared.b16 {%0,%1,%2,%3}, [%4];\n"
                 : "=r"(r0), "=r"(r1), "=r"(r2), "=r"(r3) : "r"(addr));
}
__device__ __forceinline__ void ldsm_x4t(uint32_t& r0, uint32_t& r1, uint32_t& r2, uint32_t& r3,
                                         uint32_t addr) {
    asm volatile("ldmatrix.sync.aligned.m8n8.x4.trans.shared.b16 {%0,%1,%2,%3}, [%4];\n"
                 : "=r"(r0), "=r"(r1), "=r"(r2), "=r"(r3) : "r"(addr));
}
__device__ __forceinline__ void mma_bf16(float& d0, float& d1, float& d2, float& d3,
                                         uint32_t a0, uint32_t a1, uint32_t a2, uint32_t a3,
                                         uint32_t b0, uint32_t b1) {
    asm volatile("mma.sync.aligned.m16n8k16.row.col.f32.bf16.bf16.f32 "
                 "{%0,%1,%2,%3}, {%4,%5,%6,%7}, {%8,%9}, {%0,%1,%2,%3};\n"
                 : "+f"(d0), "+f"(d1), "+f"(d2), "+f"(d3)
                 : "r"(a0), "r"(a1), "r"(a2), "r"(a3), "r"(b0), "r"(b1));
}
__device__ __forceinline__ void cp16(uint32_t dst, const void* src) {
    asm volatile("cp.async.cg.shared.global [%0], [%1], 16;\n" :: "r"(dst), "l"(src));
}

extern __shared__ char dyn_smem[];

// ---------------------------------------------------------------------------
// K3: tensor-core windowed attention; qkv head-blocked in, attn head-blocked out.
// in:  qkv[((wnd*24 + qkv_idx*8 + head) << 11) + row*32 + ch]
// out: attn[((wnd*8 + head) << 11) + row*32 + ch]
#define ATT_STRIDE 40
#define ATT_MAT    (64 * ATT_STRIDE)
#define ATT_SMEM   (3 * 4 * ATT_MAT * 2)

__global__ void __launch_bounds__(256, 2) k_attn_mma(
    const __nv_bfloat16* __restrict__ qkv, const float* __restrict__ btab,
    __nv_bfloat16* __restrict__ out) {
    int wnd  = blockIdx.x >> 1;
    int half = blockIdx.x & 1;
    int tid  = threadIdx.x;
    int lane = tid & 31;
    int warp = tid >> 5;
    int hl   = warp >> 1;
    int sub  = warp & 1;
    int head = half * 4 + hl;

    __nv_bfloat16* smQ = (__nv_bfloat16*)dyn_smem;
    __nv_bfloat16* smK = smQ + 4 * ATT_MAT;
    __nv_bfloat16* smV = smK + 4 * ATT_MAT;

    uint32_t sq = (uint32_t)__cvta_generic_to_shared(smQ + hl * ATT_MAT);
    uint32_t sk = (uint32_t)__cvta_generic_to_shared(smK + hl * ATT_MAT);
    uint32_t sv = (uint32_t)__cvta_generic_to_shared(smV + hl * ATT_MAT);

    const __nv_bfloat16* qb = qkv + (((size_t)wnd * 24 +  0 + head) << 11);
    const __nv_bfloat16* kb = qkv + (((size_t)wnd * 24 +  8 + head) << 11);
    const __nv_bfloat16* vb = qkv + (((size_t)wnd * 24 + 16 + head) << 11);
    #pragma unroll
    for (int c = 0; c < 4; c++) {
        int chunk = c * 64 + sub * 32 + lane;
        int row = chunk >> 2, grp = (chunk & 3) * 8;
        uint32_t off = (uint32_t)(row * ATT_STRIDE + grp) * 2;
        cp16(sq + off, qb + chunk * 8);
        cp16(sk + off, kb + chunk * 8);
        cp16(sv + off, vb + chunk * 8);
    }
    asm volatile("cp.async.commit_group;\n" ::: "memory");

    int widx = wnd % NWIN;
    int wd = widx / 196, rr = widx % 196, wh = rr / 14, ww = rr % 14;
    int mt = ((wd == 3) << 2) | ((wh == 13) << 1) | (ww == 13);
    const float* tb = btab + (((size_t)mt * 8 + head) << 12);

    asm volatile("cp.async.wait_group 0;\n" ::: "memory");
    __syncthreads();

    float acc[2][8][4];
    #pragma unroll
    for (int a = 0; a < 2; a++)
        #pragma unroll
        for (int bq = 0; bq < 8; bq++)
            #pragma unroll
            for (int t = 0; t < 4; t++) acc[a][bq][t] = 0.f;

    int arow = lane & 15;
    int asel = (lane >> 4) << 3;
    int br   = (lane & 7) + ((lane >> 4) << 3);
    int bkh  = ((lane >> 3) & 1) << 3;
    int m0   = sub * 32;

    #pragma unroll
    for (int ks = 0; ks < 2; ks++) {
        int k0 = ks * 16;
        uint32_t af[2][4];
        #pragma unroll
        for (int mi = 0; mi < 2; mi++)
            ldsm_x4(af[mi][0], af[mi][1], af[mi][2], af[mi][3],
                    sq + (uint32_t)((m0 + mi * 16 + arow) * ATT_STRIDE + k0 + asel) * 2);
        uint32_t bf[8][2];
        #pragma unroll
        for (int nb = 0; nb < 4; nb++)
            ldsm_x4(bf[2*nb][0], bf[2*nb][1], bf[2*nb+1][0], bf[2*nb+1][1],
                    sk + (uint32_t)((nb * 16 + br) * ATT_STRIDE + k0 + bkh) * 2);
        #pragma unroll
        for (int mi = 0; mi < 2; mi++)
            #pragma unroll
            for (int nj = 0; nj < 8; nj++)
                mma_bf16(acc[mi][nj][0], acc[mi][nj][1], acc[mi][nj][2], acc[mi][nj][3],
                         af[mi][0], af[mi][1], af[mi][2], af[mi][3], bf[nj][0], bf[nj][1]);
    }

    int r0 = lane >> 2;
    int cq = (lane & 3) * 2;

    const float scale = 0.17677669529663689f;
    #pragma unroll
    for (int mi = 0; mi < 2; mi++)
        #pragma unroll
        for (int hh = 0; hh < 2; hh++) {
            int i = m0 + mi * 16 + hh * 8 + r0;
            const float* tr = tb + i * 64 + cq;
            #pragma unroll
            for (int nj = 0; nj < 8; nj++) {
                float2 bv = __ldg((const float2*)(tr + nj * 8));
                acc[mi][nj][hh * 2 + 0] = acc[mi][nj][hh * 2 + 0] * scale + bv.x;
                acc[mi][nj][hh * 2 + 1] = acc[mi][nj][hh * 2 + 1] * scale + bv.y;
            }
        }

    float invs[2][2];
    #pragma unroll
    for (int mi = 0; mi < 2; mi++)
        #pragma unroll
        for (int hh = 0; hh < 2; hh++) {
            float m = -1e30f;
            #pragma unroll
            for (int nj = 0; nj < 8; nj++) {
                m = fmaxf(m, acc[mi][nj][hh * 2]);
                m = fmaxf(m, acc[mi][nj][hh * 2 + 1]);
            }
            m = fmaxf(m, __shfl_xor_sync(0xffffffffu, m, 1));
            m = fmaxf(m, __shfl_xor_sync(0xffffffffu, m, 2));
            float sum = 0.f;
            #pragma unroll
            for (int nj = 0; nj < 8; nj++) {
                float e0 = __expf(acc[mi][nj][hh * 2]     - m);
                float e1 = __expf(acc[mi][nj][hh * 2 + 1] - m);
                acc[mi][nj][hh * 2] = e0; acc[mi][nj][hh * 2 + 1] = e1;
                sum += e0 + e1;
            }
            sum += __shfl_xor_sync(0xffffffffu, sum, 1);
            sum += __shfl_xor_sync(0xffffffffu, sum, 2);
            invs[mi][hh] = 1.0f / sum;
        }

    uint32_t pk[2][8][2];
    #pragma unroll
    for (int mi = 0; mi < 2; mi++)
        #pragma unroll
        for (int t = 0; t < 8; t++) {
            __nv_bfloat162 p0 = __floats2bfloat162_rn(acc[mi][t][0] * invs[mi][0],
                                                      acc[mi][t][1] * invs[mi][0]);
            __nv_bfloat162 p1 = __floats2bfloat162_rn(acc[mi][t][2] * invs[mi][1],
                                                      acc[mi][t][3] * invs[mi][1]);
            pk[mi][t][0] = *(uint32_t*)&p0;
            pk[mi][t][1] = *(uint32_t*)&p1;
        }

    float o[2][4][4];
    #pragma unroll
    for (int a = 0; a < 2; a++)
        #pragma unroll
        for (int bq = 0; bq < 4; bq++)
            #pragma unroll
            for (int t = 0; t < 4; t++) o[a][bq][t] = 0.f;

    #pragma unroll
    for (int kt = 0; kt < 4; kt++) {
        uint32_t bv[4][2];
        #pragma unroll
        for (int nb = 0; nb < 2; nb++)
            ldsm_x4t(bv[2*nb][0], bv[2*nb][1], bv[2*nb+1][0], bv[2*nb+1][1],
                     sv + (uint32_t)((kt * 16 + arow) * ATT_STRIDE + nb * 16 + asel) * 2);
        #pragma unroll
        for (int mi = 0; mi < 2; mi++)
            #pragma unroll
            for (int nt = 0; nt < 4; nt++)
                mma_bf16(o[mi][nt][0], o[mi][nt][1], o[mi][nt][2], o[mi][nt][3],
                         pk[mi][2*kt][0], pk[mi][2*kt][1], pk[mi][2*kt+1][0], pk[mi][2*kt+1][1],
                         bv[nt][0], bv[nt][1]);
    }

    // head-blocked output: [(wnd*8 + head)][row][col] with 64x32 blocks
    __nv_bfloat16* ob = out + (((size_t)wnd * 8 + head) << 11);
    #pragma unroll
    for (int mi = 0; mi < 2; mi++)
        #pragma unroll
        for (int nt = 0; nt < 4; nt++)
            #pragma unroll
            for (int hh = 0; hh < 2; hh++) {
                int row = m0 + mi * 16 + hh * 8 + r0;
                int col = nt * 8 + cq;
                __nv_bfloat162 p = __floats2bfloat162_rn(o[mi][nt][hh * 2],
                                                         o[mi][nt][hh * 2 + 1]);
                *(__nv_bfloat162*)(ob + (row << 5) + col) = p;
            }
}

// ---------------------------------------------------------------------------
// bf16 tensor-core GEMM (R11 proven): 256 threads, 8 warps 4x2, warp tile 32x64,
// CTA 128x128, BK=64, 3-stage cp.async ring, warp-staggered ks order.
// EPI: 0 = bf16 out, 2 = GELU + bf16 out, 3 = +res fp32 out, 4 = head-blocked bf16 (qkv)
// ABLK: 0 = row-major A, 2 = 32-col head-blocked A (64-row groups, K/32 blocks)
#define SA_STRIDE 72
#define SB_STRIDE 136
#define ASTAGE (128 * SA_STRIDE * 2)
#define BSTAGE (64 * SB_STRIDE * 2)
#define GEMM_SMEM (3 * (ASTAGE + BSTAGE))

template<int EPI, int KN, int ABLK = 0>
__global__ void __launch_bounds__(256, 2) k_mmagemm(
    const __nv_bfloat16* __restrict__ A, const __nv_bfloat16* __restrict__ Bw,
    const float* __restrict__ bias, void* __restrict__ Cout,
    int N, const float* __restrict__ res) {
    constexpr int K = KN;
    constexpr int NIT = K >> 6;
    int tid  = threadIdx.x;
    int lane = tid & 31, warp = tid >> 5;
    int wy = warp >> 1, wx = warp & 1;
    int rowBase = blockIdx.y * 128;
    int colBase = blockIdx.x * 128;

    uint32_t sbase = (uint32_t)__cvta_generic_to_shared(dyn_smem);
    uint32_t sAs[3], sBs[3];
    #pragma unroll
    for (int s = 0; s < 3; s++) {
        sAs[s] = sbase + s * (ASTAGE + BSTAGE);
        sBs[s] = sAs[s] + ASTAGE;
    }

    auto issue = [&](int it) {
        int slot = it % 3;
        int k0 = it << 6;
        uint32_t sAu = sAs[slot], sBu = sBs[slot];
        #pragma unroll
        for (int i = 0; i < 4; i++) {
            int ch = tid + i * 256;
            int ar = ch >> 3, ac = ch & 7;
            const __nv_bfloat16* Ap;
            if (ABLK == 2) {
                int row = rowBase + ar;
                int k = k0 + ac * 8;
                Ap = A + (((size_t)(row >> 6) * (K >> 5) + (k >> 5)) << 11)
                       + ((row & 63) << 5) + (k & 31);
            } else {
                Ap = A + (size_t)(rowBase + ar) * K + k0 + ac * 8;
            }
            cp16(sAu + (uint32_t)(ar * SA_STRIDE + ac * 8) * 2, Ap);
            int bk = ch >> 4, bn = (ch & 15) * 8;
            cp16(sBu + (uint32_t)(bk * SB_STRIDE + bn) * 2,
                 Bw + (size_t)(k0 + bk) * N + colBase + bn);
        }
        asm volatile("cp.async.commit_group;\n" ::: "memory");
    };

    issue(0);
    if (NIT > 1) issue(1);

    float acc[2][8][4];
    #pragma unroll
    for (int i = 0; i < 2; i++)
        #pragma unroll
        for (int j = 0; j < 8; j++)
            #pragma unroll
            for (int t = 0; t < 4; t++) acc[i][j][t] = 0.f;

    int m0  = wy * 32;
    int n0w = wx * 64;
    int arow = lane & 15;
    int asel = (lane >> 4) << 3;
    int ksrot = warp & 3;

    for (int it = 0; it < NIT; it++) {
        if (it + 1 < NIT) asm volatile("cp.async.wait_group 1;\n" ::: "memory");
        else              asm volatile("cp.async.wait_group 0;\n" ::: "memory");
        __syncthreads();
        if (it + 2 < NIT) issue(it + 2);

        int slot = it % 3;
        uint32_t sAu = sAs[slot], sBu = sBs[slot];

        #pragma unroll
        for (int ksi = 0; ksi < 4; ksi++) {
            int ks = (ksi + ksrot) & 3;
            int k0 = ks * 16;
            uint32_t a[2][4];
            #pragma unroll
            for (int mi = 0; mi < 2; mi++)
                ldsm_x4(a[mi][0], a[mi][1], a[mi][2], a[mi][3],
                        sAu + (uint32_t)((m0 + mi * 16 + arow) * SA_STRIDE + k0 + asel) * 2);
            uint32_t b[8][2];
            #pragma unroll
            for (int nj = 0; nj < 4; nj++)
                ldsm_x4t(b[2 * nj][0], b[2 * nj][1], b[2 * nj + 1][0], b[2 * nj + 1][1],
                         sBu + (uint32_t)((k0 + (lane & 15)) * SB_STRIDE
                                          + n0w + nj * 16 + ((lane >> 4) << 3)) * 2);
            #pragma unroll
            for (int mi = 0; mi < 2; mi++)
                #pragma unroll
                for (int ni = 0; ni < 8; ni++)
                    mma_bf16(acc[mi][ni][0], acc[mi][ni][1], acc[mi][ni][2], acc[mi][ni][3],
                             a[mi][0], a[mi][1], a[mi][2], a[mi][3], b[ni][0], b[ni][1]);
        }
    }

    int gr = lane >> 2, gc = (lane & 3) * 2;
    float bias_r[8][2];
    #pragma unroll
    for (int ni = 0; ni < 8; ni++) {
        int col = colBase + n0w + ni * 8 + gc;
        bias_r[ni][0] = bias[col];
        bias_r[ni][1] = bias[col + 1];
    }
    #pragma unroll
    for (int mi = 0; mi < 2; mi++) {
        #pragma unroll
        for (int ni = 0; ni < 8; ni++) {
            int col = colBase + n0w + ni * 8 + gc;
            #pragma unroll
            for (int half = 0; half < 2; half++) {
                size_t row = (size_t)(rowBase + m0 + mi * 16 + gr + half * 8);
                float v0 = acc[mi][ni][half * 2 + 0] + bias_r[ni][0];
                float v1 = acc[mi][ni][half * 2 + 1] + bias_r[ni][1];
                if (EPI == 2) {
                    v0 = 0.5f * v0 * (1.0f + erff(v0 * 0.70710678118654752f));
                    v1 = 0.5f * v1 * (1.0f + erff(v1 * 0.70710678118654752f));
                }
                if (EPI == 3) {
                    v0 += res[row * N + col];
                    v1 += res[row * N + col + 1];
                    float2* p = (float2*)((float*)Cout + row * N + col);
                    *p = make_float2(v0, v1);
                } else if (EPI == 4) {
                    size_t addr = ((((row >> 6) * 24) + (size_t)(col >> 5)) << 11)
                                  + ((row & 63) << 5) + (col & 31);
                    *(__nv_bfloat162*)((__nv_bfloat16*)Cout + addr) =
                        __floats2bfloat162_rn(v0, v1);
                } else {
                    __nv_bfloat162* p = (__nv_bfloat162*)((__nv_bfloat16*)Cout + row * N + col);
                    *p = __floats2bfloat162_rn(v0, v1);
                }
            }
        }
    }
}

// ---------------------------------------------------------------------------
extern "C" void kernel_launch(void* const* d_in, const int* in_sizes, int n_in,
                              void* d_out, int out_size) {
    const float* x      = (const float*)d_in[0];
    const float* n1g    = (const float*)d_in[1];
    const float* n1b    = (const float*)d_in[2];
    const float* qkv_w  = (const float*)d_in[3];
    const float* qkv_b  = (const float*)d_in[4];
    const float* proj_w = (const float*)d_in[5];
    const float* proj_b = (const float*)d_in[6];
    const float* rpb    = (const float*)d_in[7];
    const float* n2g    = (const float*)d_in[8];
    const float* n2b    = (const float*)d_in[9];
    const float* fc1_w  = (const float*)d_in[10];
    const float* fc1_b  = (const float*)d_in[11];
    const float* fc2_w  = (const float*)d_in[12];
    const float* fc2_b  = (const float*)d_in[13];
    float* out = (float*)d_out;

    __nv_bfloat16 *ln, *big, *attn, *wts;
    float *x1, *btab;
    cudaGetSymbolAddress((void**)&ln,   g_ln);
    cudaGetSymbolAddress((void**)&big,  g_big);
    cudaGetSymbolAddress((void**)&attn, g_attn);
    cudaGetSymbolAddress((void**)&x1,   g_x1);
    cudaGetSymbolAddress((void**)&wts,  g_w);
    cudaGetSymbolAddress((void**)&btab, g_btab);

    cudaFuncSetAttribute(k_attn_mma, cudaFuncAttributeMaxDynamicSharedMemorySize, ATT_SMEM);
    cudaFuncSetAttribute((const void*)k_mmagemm<4, 256>,     cudaFuncAttributeMaxDynamicSharedMemorySize, GEMM_SMEM);
    cudaFuncSetAttribute((const void*)k_mmagemm<0, 256, 2>,  cudaFuncAttributeMaxDynamicSharedMemorySize, GEMM_SMEM);
    cudaFuncSetAttribute((const void*)k_mmagemm<2, 256>,     cudaFuncAttributeMaxDynamicSharedMemorySize, GEMM_SMEM);
    cudaFuncSetAttribute((const void*)k_mmagemm<3, 1024>,    cudaFuncAttributeMaxDynamicSharedMemorySize, GEMM_SMEM);

    // 0) merged prologue: weights -> bf16, bias+mask table
    k_pre<<<3136, 256>>>(qkv_w, proj_w, fc1_w, fc2_w, wts, rpb, btab);

    // 1) LN1 + roll + window partition -> ln
    k_ln1_v2<<<Tv / 8, 256>>>(x, n1g, n1b, ln);
    // 2) qkv GEMM: ln -> big (head-blocked layout)
    k_mmagemm<4, 256><<<dim3(768 / 128, Tv / 128), 256, GEMM_SMEM>>>(ln, wts + WOFF_QKV, qkv_b, big, 768, nullptr);
    // 3) attention: big (head-blocked) -> attn (head-blocked)
    k_attn_mma<<<BWIN * 2, 256, ATT_SMEM>>>(big, btab, attn);
    // 4) proj GEMM: attn (blocked A) -> ln (bf16)
    k_mmagemm<0, 256, 2><<<dim3(256 / 128, Tv / 128), 256, GEMM_SMEM>>>(attn, wts + WOFF_PROJ, proj_b, ln, 256, nullptr);
    // 5) x1 = x + reverse(roll(ln)); LN2 -> x1 (fp32), attn (bf16, natural)
    k_x1_ln2_v2<<<Tv / 8, 256>>>(x, ln, n2g, n2b, x1, attn);
    // 6) fc1 + GELU: attn -> big
    k_mmagemm<2, 256><<<dim3(1024 / 128, Tv / 128), 256, GEMM_SMEM>>>(attn, wts + WOFF_FC1, fc1_b, big, 1024, nullptr);
    // 7) fc2 + residual(x1): big -> out
    k_mmagemm<3, 1024><<<dim3(256 / 128, Tv / 128), 256, GEMM_SMEM>>>(big, wts + WOFF_FC2, fc2_b, out, 256, x1);
}

// round 15
// speedup vs baseline: 1.0697x; 1.0150x over previous
#include <cuda_runtime.h>
#include <cuda_bf16.h>
#include <math.h>
#include <stdint.h>

// Problem constants
#define Bv   2
#define Dv   16
#define Hv   56
#define Wv   56
#define Cv   256
#define NHv  8
#define HDv  32
#define WSv  4
#define SSv  2
#define NWIN 784
#define BWIN 1568
#define Tv   100352

// ---------------------------------------------------------------------------
// Scratch (device globals; no allocation allowed)
__device__ __nv_bfloat16 g_ln[(size_t)Tv * 256];     // ln1 out / proj out (bf16)
__device__ __nv_bfloat16 g_big[(size_t)Tv * 1024];   // qkv out (head-blocked) / fc1 out
__device__ __nv_bfloat16 g_attn[(size_t)Tv * 256];   // attn out (head-blocked) / ln2 out
__device__ float         g_x1[(size_t)Tv * 256];     // x1 (fp32)
__device__ __nv_bfloat16 g_w[786432];
__device__ float         g_btab[8 * 8 * 64 * 64];    // [mask-type][head][i][j]

#define WOFF_QKV  0
#define WOFF_PROJ 196608
#define WOFF_FC1  262144
#define WOFF_FC2  524288
#define WTOTAL    786432

// ---------------------------------------------------------------------------
// Merged prologue: blocks [0,3072) convert weights; blocks [3072,3136) build btab.
__global__ void k_pre(const float* __restrict__ s0, const float* __restrict__ s1,
                      const float* __restrict__ s2, const float* __restrict__ s3,
                      __nv_bfloat16* __restrict__ dst,
                      const float* __restrict__ rpb, float* __restrict__ tbl) {
    if (blockIdx.x < 3072) {
        int i = blockIdx.x * 256 + threadIdx.x;
        float v;
        if (i < WOFF_PROJ)      v = s0[i - WOFF_QKV];
        else if (i < WOFF_FC1)  v = s1[i - WOFF_PROJ];
        else if (i < WOFF_FC2)  v = s2[i - WOFF_FC1];
        else                    v = s3[i - WOFF_FC2];
        dst[i] = __float2bfloat16(v);
    } else {
        int idx = blockIdx.x - 3072;       // 0..63
        int mt = idx >> 3, h = idx & 7;
        int mtd = (mt >> 2) & 1, mth = (mt >> 1) & 1, mtw = mt & 1;
        for (int e = threadIdx.x; e < 4096; e += 256) {
            int i = e >> 6, j = e & 63;
            int zi = i >> 4, yi = (i >> 2) & 3, xi = i & 3;
            int zj = j >> 4, yj = (j >> 2) & 3, xj = j & 3;
            int bi = (zi - zj + 3) * 49 + (yi - yj + 3) * 7 + (xi - xj + 3);
            float v = rpb[bi * NHv + h];
            int ld = mtd ? (zi < 2 ? 1 : 2) : 0, ldj = mtd ? (zj < 2 ? 1 : 2) : 0;
            int lh = mth ? (yi < 2 ? 1 : 2) : 0, lhj = mth ? (yj < 2 ? 1 : 2) : 0;
            int lw = mtw ? (xi < 2 ? 1 : 2) : 0, lwj = mtw ? (xj < 2 ? 1 : 2) : 0;
            if (ld != ldj || lh != lhj || lw != lwj) v -= 100.0f;
            tbl[((mt * 8 + h) << 12) + e] = v;
        }
    }
}

// ---------------------------------------------------------------------------
// Warp-wide LN helpers
__device__ __forceinline__ void warp_ln8(const float* vin, float* vout,
                                         const float* __restrict__ g,
                                         const float* __restrict__ b, int cbase) {
    float s1 = 0.f, s2 = 0.f;
    #pragma unroll
    for (int t = 0; t < 8; t++) { s1 += vin[t]; s2 += vin[t] * vin[t]; }
    #pragma unroll
    for (int o = 16; o > 0; o >>= 1) {
        s1 += __shfl_xor_sync(0xffffffffu, s1, o);
        s2 += __shfl_xor_sync(0xffffffffu, s2, o);
    }
    float mu = s1 * (1.0f / 256.0f);
    float var = s2 * (1.0f / 256.0f) - mu * mu;
    float inv = rsqrtf(var + 1e-5f);
    float4 g0 = *(const float4*)(g + cbase);
    float4 g1 = *(const float4*)(g + cbase + 4);
    float4 b0 = *(const float4*)(b + cbase);
    float4 b1 = *(const float4*)(b + cbase + 4);
    vout[0] = (vin[0] - mu) * inv * g0.x + b0.x;
    vout[1] = (vin[1] - mu) * inv * g0.y + b0.y;
    vout[2] = (vin[2] - mu) * inv * g0.z + b0.z;
    vout[3] = (vin[3] - mu) * inv * g0.w + b0.w;
    vout[4] = (vin[4] - mu) * inv * g1.x + b1.x;
    vout[5] = (vin[5] - mu) * inv * g1.y + b1.y;
    vout[6] = (vin[6] - mu) * inv * g1.z + b1.z;
    vout[7] = (vin[7] - mu) * inv * g1.w + b1.w;
}

__device__ __forceinline__ uint4 pack8_bf16(const float* v) {
    uint4 r;
    __nv_bfloat162 p0 = __floats2bfloat162_rn(v[0], v[1]);
    __nv_bfloat162 p1 = __floats2bfloat162_rn(v[2], v[3]);
    __nv_bfloat162 p2 = __floats2bfloat162_rn(v[4], v[5]);
    __nv_bfloat162 p3 = __floats2bfloat162_rn(v[6], v[7]);
    r.x = *(uint32_t*)&p0; r.y = *(uint32_t*)&p1;
    r.z = *(uint32_t*)&p2; r.w = *(uint32_t*)&p3;
    return r;
}

__global__ void __launch_bounds__(256) k_ln1_v2(
    const float* __restrict__ x, const float* __restrict__ g,
    const float* __restrict__ bta, __nv_bfloat16* __restrict__ out) {
    int wt = blockIdx.x * 8 + (threadIdx.x >> 5);
    int lane = threadIdx.x & 31;
    int i  = wt & 63, b_ = wt >> 6;
    int b = b_ / NWIN, widx = b_ % NWIN;
    int wd = widx / 196, r = widx % 196, wh = r / 14, ww = r % 14;
    int zi = i >> 4, yi = (i >> 2) & 3, xi = i & 3;
    int d = (wd * 4 + zi + SSv) & 15;
    int h = wh * 4 + yi + SSv; if (h >= Hv) h -= Hv;
    int w = ww * 4 + xi + SSv; if (w >= Wv) w -= Wv;
    const float* row = x + ((size_t)((b * Dv + d) * Hv + h) * Wv + w) * Cv + lane * 8;
    float vin[8], vo[8];
    *(float4*)vin     = *(const float4*)row;
    *(float4*)(vin+4) = *(const float4*)(row + 4);
    warp_ln8(vin, vo, g, bta, lane * 8);
    *(uint4*)(out + (size_t)wt * Cv + lane * 8) = pack8_bf16(vo);
}

// x1 = x + reverse(roll(proj_out bf16));  LN2 -> lnout bf16
__global__ void __launch_bounds__(256) k_x1_ln2_v2(
    const float* __restrict__ x, const __nv_bfloat16* __restrict__ projout,
    const float* __restrict__ g, const float* __restrict__ bta,
    float* __restrict__ x1, __nv_bfloat16* __restrict__ lnout) {
    int t = blockIdx.x * 8 + (threadIdx.x >> 5);
    int lane = threadIdx.x & 31;
    int w = t % Wv, tmp = t / Wv;
    int h = tmp % Hv; tmp /= Hv;
    int d = tmp % Dv; int b = tmp / Dv;
    int ds = (d - SSv) & 15;
    int hs = h - SSv; if (hs < 0) hs += Hv;
    int ws = w - SSv; if (ws < 0) ws += Wv;
    int wt = ((b * NWIN + (ds >> 2) * 196 + (hs >> 2) * 14 + (ws >> 2)) << 6)
             + ((ds & 3) << 4) + ((hs & 3) << 2) + (ws & 3);
    const float* xr = x + (size_t)t * Cv + lane * 8;
    uint4 pv = *(const uint4*)(projout + (size_t)wt * Cv + lane * 8);
    __nv_bfloat162 p0 = *(__nv_bfloat162*)&pv.x;
    __nv_bfloat162 p1 = *(__nv_bfloat162*)&pv.y;
    __nv_bfloat162 p2 = *(__nv_bfloat162*)&pv.z;
    __nv_bfloat162 p3 = *(__nv_bfloat162*)&pv.w;
    float4 a0 = *(const float4*)xr;
    float4 a1 = *(const float4*)(xr + 4);
    float vin[8], vo[8];
    vin[0] = a0.x + __bfloat162float(p0.x); vin[1] = a0.y + __bfloat162float(p0.y);
    vin[2] = a0.z + __bfloat162float(p1.x); vin[3] = a0.w + __bfloat162float(p1.y);
    vin[4] = a1.x + __bfloat162float(p2.x); vin[5] = a1.y + __bfloat162float(p2.y);
    vin[6] = a1.z + __bfloat162float(p3.x); vin[7] = a1.w + __bfloat162float(p3.y);
    float* x1r = x1 + (size_t)t * Cv + lane * 8;
    *(float4*)x1r       = *(float4*)vin;
    *(float4*)(x1r + 4) = *(float4*)(vin + 4);
    warp_ln8(vin, vo, g, bta, lane * 8);
    *(uint4*)(lnout + (size_t)t * Cv + lane * 8) = pack8_bf16(vo);
}

// ---------------------------------------------------------------------------
// MMA primitives
__device__ __forceinline__ void ldsm_x4(uint32_t& r0, uint32_t& r1, uint32_t& r2, uint32_t& r3,
                                        uint32_t addr) {
    asm volatile("ldmatrix.sync.aligned.m8n8.x4.shared.b16 {%0,%1,%2,%3}, [%4];\n"
                 : "=r"(r0), "=r"(r1), "=r"(r2), "=r"(r3) : "r"(addr));
}
__device__ __forceinline__ void ldsm_x4t(uint32_t& r0, uint32_t& r1, uint32_t& r2, uint32_t& r3,
                                         uint32_t addr) {
    asm volatile("ldmatrix.sync.aligned.m8n8.x4.trans.shared.b16 {%0,%1,%2,%3}, [%4];\n"
                 : "=r"(r0), "=r"(r1), "=r"(r2), "=r"(r3) : "r"(addr));
}
__device__ __forceinline__ void mma_bf16(float& d0, float& d1, float& d2, float& d3,
                                         uint32_t a0, uint32_t a1, uint32_t a2, uint32_t a3,
                                         uint32_t b0, uint32_t b1) {
    asm volatile("mma.sync.aligned.m16n8k16.row.col.f32.bf16.bf16.f32 "
                 "{%0,%1,%2,%3}, {%4,%5,%6,%7}, {%8,%9}, {%0,%1,%2,%3};\n"
                 : "+f"(d0), "+f"(d1), "+f"(d2), "+f"(d3)
                 : "r"(a0), "r"(a1), "r"(a2), "r"(a3), "r"(b0), "r"(b1));
}
__device__ __forceinline__ void cp16(uint32_t dst, const void* src) {
    asm volatile("cp.async.cg.shared.global [%0], [%1], 16;\n" :: "r"(dst), "l"(src));
}

extern __shared__ char dyn_smem[];

// ---------------------------------------------------------------------------
// K3: attention, 128 threads / 2 heads per block, 4 CTAs/SM.
// in:  qkv[((wnd*24 + qkv_idx*8 + head) << 11) + row*32 + ch]  (head-blocked)
// out: attn[((wnd*8 + head) << 11) + row*32 + ch]              (head-blocked)
#define ATT_STRIDE 40
#define ATT_MAT    (64 * ATT_STRIDE)
#define ATT_SMEM   (3 * 2 * ATT_MAT * 2)

__global__ void __launch_bounds__(128, 4) k_attn_mma(
    const __nv_bfloat16* __restrict__ qkv, const float* __restrict__ btab,
    __nv_bfloat16* __restrict__ out) {
    int wnd  = blockIdx.x >> 2;
    int quad = blockIdx.x & 3;
    int tid  = threadIdx.x;
    int lane = tid & 31;
    int warp = tid >> 5;
    int hl   = warp >> 1;          // local head 0..1
    int sub  = warp & 1;
    int head = quad * 2 + hl;

    __nv_bfloat16* smQ = (__nv_bfloat16*)dyn_smem;
    __nv_bfloat16* smK = smQ + 2 * ATT_MAT;
    __nv_bfloat16* smV = smK + 2 * ATT_MAT;

    uint32_t sq = (uint32_t)__cvta_generic_to_shared(smQ + hl * ATT_MAT);
    uint32_t sk = (uint32_t)__cvta_generic_to_shared(smK + hl * ATT_MAT);
    uint32_t sv = (uint32_t)__cvta_generic_to_shared(smV + hl * ATT_MAT);

    const __nv_bfloat16* qb = qkv + (((size_t)wnd * 24 +  0 + head) << 11);
    const __nv_bfloat16* kb = qkv + (((size_t)wnd * 24 +  8 + head) << 11);
    const __nv_bfloat16* vb = qkv + (((size_t)wnd * 24 + 16 + head) << 11);
    #pragma unroll
    for (int c = 0; c < 4; c++) {
        int chunk = c * 64 + sub * 32 + lane;        // 0..255 per head (2 warps)
        int row = chunk >> 2, grp = (chunk & 3) * 8;
        uint32_t off = (uint32_t)(row * ATT_STRIDE + grp) * 2;
        cp16(sq + off, qb + chunk * 8);
        cp16(sk + off, kb + chunk * 8);
        cp16(sv + off, vb + chunk * 8);
    }
    asm volatile("cp.async.commit_group;\n" ::: "memory");

    int widx = wnd % NWIN;
    int wd = widx / 196, rr = widx % 196, wh = rr / 14, ww = rr % 14;
    int mt = ((wd == 3) << 2) | ((wh == 13) << 1) | (ww == 13);
    const float* tb = btab + (((size_t)mt * 8 + head) << 12);

    asm volatile("cp.async.wait_group 0;\n" ::: "memory");
    __syncthreads();

    float acc[2][8][4];
    #pragma unroll
    for (int a = 0; a < 2; a++)
        #pragma unroll
        for (int bq = 0; bq < 8; bq++)
            #pragma unroll
            for (int t = 0; t < 4; t++) acc[a][bq][t] = 0.f;

    int arow = lane & 15;
    int asel = (lane >> 4) << 3;
    int br   = (lane & 7) + ((lane >> 4) << 3);
    int bkh  = ((lane >> 3) & 1) << 3;
    int m0   = sub * 32;

    #pragma unroll
    for (int ks = 0; ks < 2; ks++) {
        int k0 = ks * 16;
        uint32_t af[2][4];
        #pragma unroll
        for (int mi = 0; mi < 2; mi++)
            ldsm_x4(af[mi][0], af[mi][1], af[mi][2], af[mi][3],
                    sq + (uint32_t)((m0 + mi * 16 + arow) * ATT_STRIDE + k0 + asel) * 2);
        uint32_t bf[8][2];
        #pragma unroll
        for (int nb = 0; nb < 4; nb++)
            ldsm_x4(bf[2*nb][0], bf[2*nb][1], bf[2*nb+1][0], bf[2*nb+1][1],
                    sk + (uint32_t)((nb * 16 + br) * ATT_STRIDE + k0 + bkh) * 2);
        #pragma unroll
        for (int mi = 0; mi < 2; mi++)
            #pragma unroll
            for (int nj = 0; nj < 8; nj++)
                mma_bf16(acc[mi][nj][0], acc[mi][nj][1], acc[mi][nj][2], acc[mi][nj][3],
                         af[mi][0], af[mi][1], af[mi][2], af[mi][3], bf[nj][0], bf[nj][1]);
    }

    int r0 = lane >> 2;
    int cq = (lane & 3) * 2;

    const float scale = 0.17677669529663689f;
    #pragma unroll
    for (int mi = 0; mi < 2; mi++)
        #pragma unroll
        for (int hh = 0; hh < 2; hh++) {
            int i = m0 + mi * 16 + hh * 8 + r0;
            const float* tr = tb + i * 64 + cq;
            #pragma unroll
            for (int nj = 0; nj < 8; nj++) {
                float2 bv = __ldg((const float2*)(tr + nj * 8));
                acc[mi][nj][hh * 2 + 0] = acc[mi][nj][hh * 2 + 0] * scale + bv.x;
                acc[mi][nj][hh * 2 + 1] = acc[mi][nj][hh * 2 + 1] * scale + bv.y;
            }
        }

    float invs[2][2];
    #pragma unroll
    for (int mi = 0; mi < 2; mi++)
        #pragma unroll
        for (int hh = 0; hh < 2; hh++) {
            float m = -1e30f;
            #pragma unroll
            for (int nj = 0; nj < 8; nj++) {
                m = fmaxf(m, acc[mi][nj][hh * 2]);
                m = fmaxf(m, acc[mi][nj][hh * 2 + 1]);
            }
            m = fmaxf(m, __shfl_xor_sync(0xffffffffu, m, 1));
            m = fmaxf(m, __shfl_xor_sync(0xffffffffu, m, 2));
            float sum = 0.f;
            #pragma unroll
            for (int nj = 0; nj < 8; nj++) {
                float e0 = __expf(acc[mi][nj][hh * 2]     - m);
                float e1 = __expf(acc[mi][nj][hh * 2 + 1] - m);
                acc[mi][nj][hh * 2] = e0; acc[mi][nj][hh * 2 + 1] = e1;
                sum += e0 + e1;
            }
            sum += __shfl_xor_sync(0xffffffffu, sum, 1);
            sum += __shfl_xor_sync(0xffffffffu, sum, 2);
            invs[mi][hh] = 1.0f / sum;
        }

    uint32_t pk[2][8][2];
    #pragma unroll
    for (int mi = 0; mi < 2; mi++)
        #pragma unroll
        for (int t = 0; t < 8; t++) {
            __nv_bfloat162 p0 = __floats2bfloat162_rn(acc[mi][t][0] * invs[mi][0],
                                                      acc[mi][t][1] * invs[mi][0]);
            __nv_bfloat162 p1 = __floats2bfloat162_rn(acc[mi][t][2] * invs[mi][1],
                                                      acc[mi][t][3] * invs[mi][1]);
            pk[mi][t][0] = *(uint32_t*)&p0;
            pk[mi][t][1] = *(uint32_t*)&p1;
        }

    float o[2][4][4];
    #pragma unroll
    for (int a = 0; a < 2; a++)
        #pragma unroll
        for (int bq = 0; bq < 4; bq++)
            #pragma unroll
            for (int t = 0; t < 4; t++) o[a][bq][t] = 0.f;

    #pragma unroll
    for (int kt = 0; kt < 4; kt++) {
        uint32_t bv[4][2];
        #pragma unroll
        for (int nb = 0; nb < 2; nb++)
            ldsm_x4t(bv[2*nb][0], bv[2*nb][1], bv[2*nb+1][0], bv[2*nb+1][1],
                     sv + (uint32_t)((kt * 16 + arow) * ATT_STRIDE + nb * 16 + asel) * 2);
        #pragma unroll
        for (int mi = 0; mi < 2; mi++)
            #pragma unroll
            for (int nt = 0; nt < 4; nt++)
                mma_bf16(o[mi][nt][0], o[mi][nt][1], o[mi][nt][2], o[mi][nt][3],
                         pk[mi][2*kt][0], pk[mi][2*kt][1], pk[mi][2*kt+1][0], pk[mi][2*kt+1][1],
                         bv[nt][0], bv[nt][1]);
    }

    // head-blocked output
    __nv_bfloat16* ob = out + (((size_t)wnd * 8 + head) << 11);
    #pragma unroll
    for (int mi = 0; mi < 2; mi++)
        #pragma unroll
        for (int nt = 0; nt < 4; nt++)
            #pragma unroll
            for (int hh = 0; hh < 2; hh++) {
                int row = m0 + mi * 16 + hh * 8 + r0;
                int col = nt * 8 + cq;
                __nv_bfloat162 p = __floats2bfloat162_rn(o[mi][nt][hh * 2],
                                                         o[mi][nt][hh * 2 + 1]);
                *(__nv_bfloat162*)(ob + (row << 5) + col) = p;
            }
}

// ---------------------------------------------------------------------------
// bf16 tensor-core GEMM (R11 proven): 256 threads, 8 warps 4x2, warp tile 32x64,
// CTA 128x128, BK=64, 3-stage cp.async ring, warp-staggered ks order.
// EPI: 0 = bf16 out, 2 = GELU + bf16 out, 3 = +res fp32 out, 4 = head-blocked bf16 (qkv)
// ABLK: 0 = row-major A, 2 = 32-col head-blocked A
#define SA_STRIDE 72
#define SB_STRIDE 136
#define ASTAGE (128 * SA_STRIDE * 2)
#define BSTAGE (64 * SB_STRIDE * 2)
#define GEMM_SMEM (3 * (ASTAGE + BSTAGE))

template<int EPI, int KN, int ABLK = 0>
__global__ void __launch_bounds__(256, 2) k_mmagemm(
    const __nv_bfloat16* __restrict__ A, const __nv_bfloat16* __restrict__ Bw,
    const float* __restrict__ bias, void* __restrict__ Cout,
    int N, const float* __restrict__ res) {
    constexpr int K = KN;
    constexpr int NIT = K >> 6;
    int tid  = threadIdx.x;
    int lane = tid & 31, warp = tid >> 5;
    int wy = warp >> 1, wx = warp & 1;
    int rowBase = blockIdx.y * 128;
    int colBase = blockIdx.x * 128;

    uint32_t sbase = (uint32_t)__cvta_generic_to_shared(dyn_smem);
    uint32_t sAs[3], sBs[3];
    #pragma unroll
    for (int s = 0; s < 3; s++) {
        sAs[s] = sbase + s * (ASTAGE + BSTAGE);
        sBs[s] = sAs[s] + ASTAGE;
    }

    auto issue = [&](int it) {
        int slot = it % 3;
        int k0 = it << 6;
        uint32_t sAu = sAs[slot], sBu = sBs[slot];
        #pragma unroll
        for (int i = 0; i < 4; i++) {
            int ch = tid + i * 256;
            int ar = ch >> 3, ac = ch & 7;
            const __nv_bfloat16* Ap;
            if (ABLK == 2) {
                int row = rowBase + ar;
                int k = k0 + ac * 8;
                Ap = A + (((size_t)(row >> 6) * (K >> 5) + (k >> 5)) << 11)
                       + ((row & 63) << 5) + (k & 31);
            } else {
                Ap = A + (size_t)(rowBase + ar) * K + k0 + ac * 8;
            }
            cp16(sAu + (uint32_t)(ar * SA_STRIDE + ac * 8) * 2, Ap);
            int bk = ch >> 4, bn = (ch & 15) * 8;
            cp16(sBu + (uint32_t)(bk * SB_STRIDE + bn) * 2,
                 Bw + (size_t)(k0 + bk) * N + colBase + bn);
        }
        asm volatile("cp.async.commit_group;\n" ::: "memory");
    };

    issue(0);
    if (NIT > 1) issue(1);

    float acc[2][8][4];
    #pragma unroll
    for (int i = 0; i < 2; i++)
        #pragma unroll
        for (int j = 0; j < 8; j++)
            #pragma unroll
            for (int t = 0; t < 4; t++) acc[i][j][t] = 0.f;

    int m0  = wy * 32;
    int n0w = wx * 64;
    int arow = lane & 15;
    int asel = (lane >> 4) << 3;
    int ksrot = warp & 3;

    for (int it = 0; it < NIT; it++) {
        if (it + 1 < NIT) asm volatile("cp.async.wait_group 1;\n" ::: "memory");
        else              asm volatile("cp.async.wait_group 0;\n" ::: "memory");
        __syncthreads();
        if (it + 2 < NIT) issue(it + 2);

        int slot = it % 3;
        uint32_t sAu = sAs[slot], sBu = sBs[slot];

        #pragma unroll
        for (int ksi = 0; ksi < 4; ksi++) {
            int ks = (ksi + ksrot) & 3;
            int k0 = ks * 16;
            uint32_t a[2][4];
            #pragma unroll
            for (int mi = 0; mi < 2; mi++)
                ldsm_x4(a[mi][0], a[mi][1], a[mi][2], a[mi][3],
                        sAu + (uint32_t)((m0 + mi * 16 + arow) * SA_STRIDE + k0 + asel) * 2);
            uint32_t b[8][2];
            #pragma unroll
            for (int nj = 0; nj < 4; nj++)
                ldsm_x4t(b[2 * nj][0], b[2 * nj][1], b[2 * nj + 1][0], b[2 * nj + 1][1],
                         sBu + (uint32_t)((k0 + (lane & 15)) * SB_STRIDE
                                          + n0w + nj * 16 + ((lane >> 4) << 3)) * 2);
            #pragma unroll
            for (int mi = 0; mi < 2; mi++)
                #pragma unroll
                for (int ni = 0; ni < 8; ni++)
                    mma_bf16(acc[mi][ni][0], acc[mi][ni][1], acc[mi][ni][2], acc[mi][ni][3],
                             a[mi][0], a[mi][1], a[mi][2], a[mi][3], b[ni][0], b[ni][1]);
        }
    }

    int gr = lane >> 2, gc = (lane & 3) * 2;
    float bias_r[8][2];
    #pragma unroll
    for (int ni = 0; ni < 8; ni++) {
        int col = colBase + n0w + ni * 8 + gc;
        bias_r[ni][0] = bias[col];
        bias_r[ni][1] = bias[col + 1];
    }
    #pragma unroll
    for (int mi = 0; mi < 2; mi++) {
        #pragma unroll
        for (int ni = 0; ni < 8; ni++) {
            int col = colBase + n0w + ni * 8 + gc;
            #pragma unroll
            for (int half = 0; half < 2; half++) {
                size_t row = (size_t)(rowBase + m0 + mi * 16 + gr + half * 8);
                float v0 = acc[mi][ni][half * 2 + 0] + bias_r[ni][0];
                float v1 = acc[mi][ni][half * 2 + 1] + bias_r[ni][1];
                if (EPI == 2) {
                    v0 = 0.5f * v0 * (1.0f + erff(v0 * 0.70710678118654752f));
                    v1 = 0.5f * v1 * (1.0f + erff(v1 * 0.70710678118654752f));
                }
                if (EPI == 3) {
                    v0 += res[row * N + col];
                    v1 += res[row * N + col + 1];
                    float2* p = (float2*)((float*)Cout + row * N + col);
                    *p = make_float2(v0, v1);
                } else if (EPI == 4) {
                    size_t addr = ((((row >> 6) * 24) + (size_t)(col >> 5)) << 11)
                                  + ((row & 63) << 5) + (col & 31);
                    *(__nv_bfloat162*)((__nv_bfloat16*)Cout + addr) =
                        __floats2bfloat162_rn(v0, v1);
                } else {
                    __nv_bfloat162* p = (__nv_bfloat162*)((__nv_bfloat16*)Cout + row * N + col);
                    *p = __floats2bfloat162_rn(v0, v1);
                }
            }
        }
    }
}

// ---------------------------------------------------------------------------
extern "C" void kernel_launch(void* const* d_in, const int* in_sizes, int n_in,
                              void* d_out, int out_size) {
    const float* x      = (const float*)d_in[0];
    const float* n1g    = (const float*)d_in[1];
    const float* n1b    = (const float*)d_in[2];
    const float* qkv_w  = (const float*)d_in[3];
    const float* qkv_b  = (const float*)d_in[4];
    const float* proj_w = (const float*)d_in[5];
    const float* proj_b = (const float*)d_in[6];
    const float* rpb    = (const float*)d_in[7];
    const float* n2g    = (const float*)d_in[8];
    const float* n2b    = (const float*)d_in[9];
    const float* fc1_w  = (const float*)d_in[10];
    const float* fc1_b  = (const float*)d_in[11];
    const float* fc2_w  = (const float*)d_in[12];
    const float* fc2_b  = (const float*)d_in[13];
    float* out = (float*)d_out;

    __nv_bfloat16 *ln, *big, *attn, *wts;
    float *x1, *btab;
    cudaGetSymbolAddress((void**)&ln,   g_ln);
    cudaGetSymbolAddress((void**)&big,  g_big);
    cudaGetSymbolAddress((void**)&attn, g_attn);
    cudaGetSymbolAddress((void**)&x1,   g_x1);
    cudaGetSymbolAddress((void**)&wts,  g_w);
    cudaGetSymbolAddress((void**)&btab, g_btab);

    cudaFuncSetAttribute(k_attn_mma, cudaFuncAttributeMaxDynamicSharedMemorySize, ATT_SMEM);
    cudaFuncSetAttribute((const void*)k_mmagemm<4, 256>,     cudaFuncAttributeMaxDynamicSharedMemorySize, GEMM_SMEM);
    cudaFuncSetAttribute((const void*)k_mmagemm<0, 256, 2>,  cudaFuncAttributeMaxDynamicSharedMemorySize, GEMM_SMEM);
    cudaFuncSetAttribute((const void*)k_mmagemm<2, 256>,     cudaFuncAttributeMaxDynamicSharedMemorySize, GEMM_SMEM);
    cudaFuncSetAttribute((const void*)k_mmagemm<3, 1024>,    cudaFuncAttributeMaxDynamicSharedMemorySize, GEMM_SMEM);

    // 0) merged prologue: weights -> bf16, bias+mask table
    k_pre<<<3136, 256>>>(qkv_w, proj_w, fc1_w, fc2_w, wts, rpb, btab);

    // 1) LN1 + roll + window partition -> ln
    k_ln1_v2<<<Tv / 8, 256>>>(x, n1g, n1b, ln);
    // 2) qkv GEMM: ln -> big (head-blocked layout)
    k_mmagemm<4, 256><<<dim3(768 / 128, Tv / 128), 256, GEMM_SMEM>>>(ln, wts + WOFF_QKV, qkv_b, big, 768, nullptr);
    // 3) attention (2 heads/block, 4 CTAs/SM): big -> attn (head-blocked)
    k_attn_mma<<<BWIN * 4, 128, ATT_SMEM>>>(big, btab, attn);
    // 4) proj GEMM: attn (blocked A) -> ln (bf16)
    k_mmagemm<0, 256, 2><<<dim3(256 / 128, Tv / 128), 256, GEMM_SMEM>>>(attn, wts + WOFF_PROJ, proj_b, ln, 256, nullptr);
    // 5) x1 = x + reverse(roll(ln)); LN2 -> x1 (fp32), attn (bf16, natural)
    k_x1_ln2_v2<<<Tv / 8, 256>>>(x, ln, n2g, n2b, x1, attn);
    // 6) fc1 + GELU: attn -> big
    k_mmagemm<2, 256><<<dim3(1024 / 128, Tv / 128), 256, GEMM_SMEM>>>(attn, wts + WOFF_FC1, fc1_b, big, 1024, nullptr);
    // 7) fc2 + residual(x1): big -> out
    k_mmagemm<3, 1024><<<dim3(256 / 128, Tv / 128), 256, GEMM_SMEM>>>(big, wts + WOFF_FC2, fc2_b, out, 256, x1);
}

// round 16
// speedup vs baseline: 1.0706x; 1.0008x over previous
#include <cuda_runtime.h>
#include <cuda_bf16.h>
#include <math.h>
#include <stdint.h>

// Problem constants
#define Bv   2
#define Dv   16
#define Hv   56
#define Wv   56
#define Cv   256
#define NHv  8
#define HDv  32
#define WSv  4
#define SSv  2
#define NWIN 784
#define BWIN 1568
#define Tv   100352

// ---------------------------------------------------------------------------
// Scratch (device globals; no allocation allowed)
__device__ __nv_bfloat16 g_ln[(size_t)Tv * 256];     // ln1 out / proj out (bf16)
__device__ __nv_bfloat16 g_big[(size_t)Tv * 1024];   // qkv out (head-blocked) / fc1 out
__device__ __nv_bfloat16 g_attn[(size_t)Tv * 256];   // attn out (head-blocked) / ln2 out
__device__ float         g_x1[(size_t)Tv * 256];     // x1 (fp32)
__device__ __nv_bfloat16 g_w[786432];
__device__ float         g_btab[8 * 8 * 64 * 64];    // [mask-type][head][i][j]

#define WOFF_QKV  0
#define WOFF_PROJ 196608
#define WOFF_FC1  262144
#define WOFF_FC2  524288
#define WTOTAL    786432

// ---------------------------------------------------------------------------
// Merged prologue: blocks [0,3072) convert weights; blocks [3072,3136) build btab.
__global__ void k_pre(const float* __restrict__ s0, const float* __restrict__ s1,
                      const float* __restrict__ s2, const float* __restrict__ s3,
                      __nv_bfloat16* __restrict__ dst,
                      const float* __restrict__ rpb, float* __restrict__ tbl) {
    if (blockIdx.x < 3072) {
        int i = blockIdx.x * 256 + threadIdx.x;
        float v;
        if (i < WOFF_PROJ)      v = s0[i - WOFF_QKV];
        else if (i < WOFF_FC1)  v = s1[i - WOFF_PROJ];
        else if (i < WOFF_FC2)  v = s2[i - WOFF_FC1];
        else                    v = s3[i - WOFF_FC2];
        dst[i] = __float2bfloat16(v);
    } else {
        int idx = blockIdx.x - 3072;       // 0..63
        int mt = idx >> 3, h = idx & 7;
        int mtd = (mt >> 2) & 1, mth = (mt >> 1) & 1, mtw = mt & 1;
        for (int e = threadIdx.x; e < 4096; e += 256) {
            int i = e >> 6, j = e & 63;
            int zi = i >> 4, yi = (i >> 2) & 3, xi = i & 3;
            int zj = j >> 4, yj = (j >> 2) & 3, xj = j & 3;
            int bi = (zi - zj + 3) * 49 + (yi - yj + 3) * 7 + (xi - xj + 3);
            float v = rpb[bi * NHv + h];
            int ld = mtd ? (zi < 2 ? 1 : 2) : 0, ldj = mtd ? (zj < 2 ? 1 : 2) : 0;
            int lh = mth ? (yi < 2 ? 1 : 2) : 0, lhj = mth ? (yj < 2 ? 1 : 2) : 0;
            int lw = mtw ? (xi < 2 ? 1 : 2) : 0, lwj = mtw ? (xj < 2 ? 1 : 2) : 0;
            if (ld != ldj || lh != lhj || lw != lwj) v -= 100.0f;
            tbl[((mt * 8 + h) << 12) + e] = v;
        }
    }
}

// ---------------------------------------------------------------------------
// Warp-wide LN helpers
__device__ __forceinline__ void warp_ln8(const float* vin, float* vout,
                                         const float* __restrict__ g,
                                         const float* __restrict__ b, int cbase) {
    float s1 = 0.f, s2 = 0.f;
    #pragma unroll
    for (int t = 0; t < 8; t++) { s1 += vin[t]; s2 += vin[t] * vin[t]; }
    #pragma unroll
    for (int o = 16; o > 0; o >>= 1) {
        s1 += __shfl_xor_sync(0xffffffffu, s1, o);
        s2 += __shfl_xor_sync(0xffffffffu, s2, o);
    }
    float mu = s1 * (1.0f / 256.0f);
    float var = s2 * (1.0f / 256.0f) - mu * mu;
    float inv = rsqrtf(var + 1e-5f);
    float4 g0 = *(const float4*)(g + cbase);
    float4 g1 = *(const float4*)(g + cbase + 4);
    float4 b0 = *(const float4*)(b + cbase);
    float4 b1 = *(const float4*)(b + cbase + 4);
    vout[0] = (vin[0] - mu) * inv * g0.x + b0.x;
    vout[1] = (vin[1] - mu) * inv * g0.y + b0.y;
    vout[2] = (vin[2] - mu) * inv * g0.z + b0.z;
    vout[3] = (vin[3] - mu) * inv * g0.w + b0.w;
    vout[4] = (vin[4] - mu) * inv * g1.x + b1.x;
    vout[5] = (vin[5] - mu) * inv * g1.y + b1.y;
    vout[6] = (vin[6] - mu) * inv * g1.z + b1.z;
    vout[7] = (vin[7] - mu) * inv * g1.w + b1.w;
}

__device__ __forceinline__ uint4 pack8_bf16(const float* v) {
    uint4 r;
    __nv_bfloat162 p0 = __floats2bfloat162_rn(v[0], v[1]);
    __nv_bfloat162 p1 = __floats2bfloat162_rn(v[2], v[3]);
    __nv_bfloat162 p2 = __floats2bfloat162_rn(v[4], v[5]);
    __nv_bfloat162 p3 = __floats2bfloat162_rn(v[6], v[7]);
    r.x = *(uint32_t*)&p0; r.y = *(uint32_t*)&p1;
    r.z = *(uint32_t*)&p2; r.w = *(uint32_t*)&p3;
    return r;
}

__global__ void __launch_bounds__(256) k_ln1_v2(
    const float* __restrict__ x, const float* __restrict__ g,
    const float* __restrict__ bta, __nv_bfloat16* __restrict__ out) {
    int wt = blockIdx.x * 8 + (threadIdx.x >> 5);
    int lane = threadIdx.x & 31;
    int i  = wt & 63, b_ = wt >> 6;
    int b = b_ / NWIN, widx = b_ % NWIN;
    int wd = widx / 196, r = widx % 196, wh = r / 14, ww = r % 14;
    int zi = i >> 4, yi = (i >> 2) & 3, xi = i & 3;
    int d = (wd * 4 + zi + SSv) & 15;
    int h = wh * 4 + yi + SSv; if (h >= Hv) h -= Hv;
    int w = ww * 4 + xi + SSv; if (w >= Wv) w -= Wv;
    const float* row = x + ((size_t)((b * Dv + d) * Hv + h) * Wv + w) * Cv + lane * 8;
    float vin[8], vo[8];
    *(float4*)vin     = *(const float4*)row;
    *(float4*)(vin+4) = *(const float4*)(row + 4);
    warp_ln8(vin, vo, g, bta, lane * 8);
    *(uint4*)(out + (size_t)wt * Cv + lane * 8) = pack8_bf16(vo);
}

// x1 = x + reverse(roll(proj_out bf16));  LN2 -> lnout bf16
__global__ void __launch_bounds__(256) k_x1_ln2_v2(
    const float* __restrict__ x, const __nv_bfloat16* __restrict__ projout,
    const float* __restrict__ g, const float* __restrict__ bta,
    float* __restrict__ x1, __nv_bfloat16* __restrict__ lnout) {
    int t = blockIdx.x * 8 + (threadIdx.x >> 5);
    int lane = threadIdx.x & 31;
    int w = t % Wv, tmp = t / Wv;
    int h = tmp % Hv; tmp /= Hv;
    int d = tmp % Dv; int b = tmp / Dv;
    int ds = (d - SSv) & 15;
    int hs = h - SSv; if (hs < 0) hs += Hv;
    int ws = w - SSv; if (ws < 0) ws += Wv;
    int wt = ((b * NWIN + (ds >> 2) * 196 + (hs >> 2) * 14 + (ws >> 2)) << 6)
             + ((ds & 3) << 4) + ((hs & 3) << 2) + (ws & 3);
    const float* xr = x + (size_t)t * Cv + lane * 8;
    uint4 pv = *(const uint4*)(projout + (size_t)wt * Cv + lane * 8);
    __nv_bfloat162 p0 = *(__nv_bfloat162*)&pv.x;
    __nv_bfloat162 p1 = *(__nv_bfloat162*)&pv.y;
    __nv_bfloat162 p2 = *(__nv_bfloat162*)&pv.z;
    __nv_bfloat162 p3 = *(__nv_bfloat162*)&pv.w;
    float4 a0 = *(const float4*)xr;
    float4 a1 = *(const float4*)(xr + 4);
    float vin[8], vo[8];
    vin[0] = a0.x + __bfloat162float(p0.x); vin[1] = a0.y + __bfloat162float(p0.y);
    vin[2] = a0.z + __bfloat162float(p1.x); vin[3] = a0.w + __bfloat162float(p1.y);
    vin[4] = a1.x + __bfloat162float(p2.x); vin[5] = a1.y + __bfloat162float(p2.y);
    vin[6] = a1.z + __bfloat162float(p3.x); vin[7] = a1.w + __bfloat162float(p3.y);
    float* x1r = x1 + (size_t)t * Cv + lane * 8;
    *(float4*)x1r       = *(float4*)vin;
    *(float4*)(x1r + 4) = *(float4*)(vin + 4);
    warp_ln8(vin, vo, g, bta, lane * 8);
    *(uint4*)(lnout + (size_t)t * Cv + lane * 8) = pack8_bf16(vo);
}

// ---------------------------------------------------------------------------
// MMA primitives
__device__ __forceinline__ void ldsm_x4(uint32_t& r0, uint32_t& r1, uint32_t& r2, uint32_t& r3,
                                        uint32_t addr) {
    asm volatile("ldmatrix.sync.aligned.m8n8.x4.shared.b16 {%0,%1,%2,%3}, [%4];\n"
                 : "=r"(r0), "=r"(r1), "=r"(r2), "=r"(r3) : "r"(addr));
}
__device__ __forceinline__ void ldsm_x4t(uint32_t& r0, uint32_t& r1, uint32_t& r2, uint32_t& r3,
                                         uint32_t addr) {
    asm volatile("ldmatrix.sync.aligned.m8n8.x4.trans.shared.b16 {%0,%1,%2,%3}, [%4];\n"
                 : "=r"(r0), "=r"(r1), "=r"(r2), "=r"(r3) : "r"(addr));
}
__device__ __forceinline__ void mma_bf16(float& d0, float& d1, float& d2, float& d3,
                                         uint32_t a0, uint32_t a1, uint32_t a2, uint32_t a3,
                                         uint32_t b0, uint32_t b1) {
    asm volatile("mma.sync.aligned.m16n8k16.row.col.f32.bf16.bf16.f32 "
                 "{%0,%1,%2,%3}, {%4,%5,%6,%7}, {%8,%9}, {%0,%1,%2,%3};\n"
                 : "+f"(d0), "+f"(d1), "+f"(d2), "+f"(d3)
                 : "r"(a0), "r"(a1), "r"(a2), "r"(a3), "r"(b0), "r"(b1));
}
__device__ __forceinline__ void cp16(uint32_t dst, const void* src) {
    asm volatile("cp.async.cg.shared.global [%0], [%1], 16;\n" :: "r"(dst), "l"(src));
}

extern __shared__ char dyn_smem[];

// ---------------------------------------------------------------------------
// K3: attention, 64 threads / 1 head per block, 8 CTAs/SM.
// in:  qkv[((wnd*24 + qkv_idx*8 + head) << 11) + row*32 + ch]  (head-blocked)
// out: attn[((wnd*8 + head) << 11) + row*32 + ch]              (head-blocked)
#define ATT_STRIDE 40
#define ATT_MAT    (64 * ATT_STRIDE)
#define ATT_SMEM   (3 * ATT_MAT * 2)

__global__ void __launch_bounds__(64, 8) k_attn_mma(
    const __nv_bfloat16* __restrict__ qkv, const float* __restrict__ btab,
    __nv_bfloat16* __restrict__ out) {
    int wnd  = blockIdx.x >> 3;
    int head = blockIdx.x & 7;
    int tid  = threadIdx.x;
    int lane = tid & 31;
    int sub  = tid >> 5;           // warp 0/1 = row half

    __nv_bfloat16* smQ = (__nv_bfloat16*)dyn_smem;
    __nv_bfloat16* smK = smQ + ATT_MAT;
    __nv_bfloat16* smV = smK + ATT_MAT;

    uint32_t sq = (uint32_t)__cvta_generic_to_shared(smQ);
    uint32_t sk = (uint32_t)__cvta_generic_to_shared(smK);
    uint32_t sv = (uint32_t)__cvta_generic_to_shared(smV);

    const __nv_bfloat16* qb = qkv + (((size_t)wnd * 24 +  0 + head) << 11);
    const __nv_bfloat16* kb = qkv + (((size_t)wnd * 24 +  8 + head) << 11);
    const __nv_bfloat16* vb = qkv + (((size_t)wnd * 24 + 16 + head) << 11);
    #pragma unroll
    for (int c = 0; c < 4; c++) {
        int chunk = c * 64 + tid;                    // 0..255
        int row = chunk >> 2, grp = (chunk & 3) * 8;
        uint32_t off = (uint32_t)(row * ATT_STRIDE + grp) * 2;
        cp16(sq + off, qb + chunk * 8);
        cp16(sk + off, kb + chunk * 8);
        cp16(sv + off, vb + chunk * 8);
    }
    asm volatile("cp.async.commit_group;\n" ::: "memory");

    int widx = wnd % NWIN;
    int wd = widx / 196, rr = widx % 196, wh = rr / 14, ww = rr % 14;
    int mt = ((wd == 3) << 2) | ((wh == 13) << 1) | (ww == 13);
    const float* tb = btab + (((size_t)mt * 8 + head) << 12);

    asm volatile("cp.async.wait_group 0;\n" ::: "memory");
    __syncthreads();

    float acc[2][8][4];
    #pragma unroll
    for (int a = 0; a < 2; a++)
        #pragma unroll
        for (int bq = 0; bq < 8; bq++)
            #pragma unroll
            for (int t = 0; t < 4; t++) acc[a][bq][t] = 0.f;

    int arow = lane & 15;
    int asel = (lane >> 4) << 3;
    int br   = (lane & 7) + ((lane >> 4) << 3);
    int bkh  = ((lane >> 3) & 1) << 3;
    int m0   = sub * 32;

    #pragma unroll
    for (int ks = 0; ks < 2; ks++) {
        int k0 = ks * 16;
        uint32_t af[2][4];
        #pragma unroll
        for (int mi = 0; mi < 2; mi++)
            ldsm_x4(af[mi][0], af[mi][1], af[mi][2], af[mi][3],
                    sq + (uint32_t)((m0 + mi * 16 + arow) * ATT_STRIDE + k0 + asel) * 2);
        uint32_t bf[8][2];
        #pragma unroll
        for (int nb = 0; nb < 4; nb++)
            ldsm_x4(bf[2*nb][0], bf[2*nb][1], bf[2*nb+1][0], bf[2*nb+1][1],
                    sk + (uint32_t)((nb * 16 + br) * ATT_STRIDE + k0 + bkh) * 2);
        #pragma unroll
        for (int mi = 0; mi < 2; mi++)
            #pragma unroll
            for (int nj = 0; nj < 8; nj++)
                mma_bf16(acc[mi][nj][0], acc[mi][nj][1], acc[mi][nj][2], acc[mi][nj][3],
                         af[mi][0], af[mi][1], af[mi][2], af[mi][3], bf[nj][0], bf[nj][1]);
    }

    int r0 = lane >> 2;
    int cq = (lane & 3) * 2;

    const float scale = 0.17677669529663689f;
    #pragma unroll
    for (int mi = 0; mi < 2; mi++)
        #pragma unroll
        for (int hh = 0; hh < 2; hh++) {
            int i = m0 + mi * 16 + hh * 8 + r0;
            const float* tr = tb + i * 64 + cq;
            #pragma unroll
            for (int nj = 0; nj < 8; nj++) {
                float2 bv = __ldg((const float2*)(tr + nj * 8));
                acc[mi][nj][hh * 2 + 0] = acc[mi][nj][hh * 2 + 0] * scale + bv.x;
                acc[mi][nj][hh * 2 + 1] = acc[mi][nj][hh * 2 + 1] * scale + bv.y;
            }
        }

    float invs[2][2];
    #pragma unroll
    for (int mi = 0; mi < 2; mi++)
        #pragma unroll
        for (int hh = 0; hh < 2; hh++) {
            float m = -1e30f;
            #pragma unroll
            for (int nj = 0; nj < 8; nj++) {
                m = fmaxf(m, acc[mi][nj][hh * 2]);
                m = fmaxf(m, acc[mi][nj][hh * 2 + 1]);
            }
            m = fmaxf(m, __shfl_xor_sync(0xffffffffu, m, 1));
            m = fmaxf(m, __shfl_xor_sync(0xffffffffu, m, 2));
            float sum = 0.f;
            #pragma unroll
            for (int nj = 0; nj < 8; nj++) {
                float e0 = __expf(acc[mi][nj][hh * 2]     - m);
                float e1 = __expf(acc[mi][nj][hh * 2 + 1] - m);
                acc[mi][nj][hh * 2] = e0; acc[mi][nj][hh * 2 + 1] = e1;
                sum += e0 + e1;
            }
            sum += __shfl_xor_sync(0xffffffffu, sum, 1);
            sum += __shfl_xor_sync(0xffffffffu, sum, 2);
            invs[mi][hh] = 1.0f / sum;
        }

    uint32_t pk[2][8][2];
    #pragma unroll
    for (int mi = 0; mi < 2; mi++)
        #pragma unroll
        for (int t = 0; t < 8; t++) {
            __nv_bfloat162 p0 = __floats2bfloat162_rn(acc[mi][t][0] * invs[mi][0],
                                                      acc[mi][t][1] * invs[mi][0]);
            __nv_bfloat162 p1 = __floats2bfloat162_rn(acc[mi][t][2] * invs[mi][1],
                                                      acc[mi][t][3] * invs[mi][1]);
            pk[mi][t][0] = *(uint32_t*)&p0;
            pk[mi][t][1] = *(uint32_t*)&p1;
        }

    float o[2][4][4];
    #pragma unroll
    for (int a = 0; a < 2; a++)
        #pragma unroll
        for (int bq = 0; bq < 4; bq++)
            #pragma unroll
            for (int t = 0; t < 4; t++) o[a][bq][t] = 0.f;

    #pragma unroll
    for (int kt = 0; kt < 4; kt++) {
        uint32_t bv[4][2];
        #pragma unroll
        for (int nb = 0; nb < 2; nb++)
            ldsm_x4t(bv[2*nb][0], bv[2*nb][1], bv[2*nb+1][0], bv[2*nb+1][1],
                     sv + (uint32_t)((kt * 16 + arow) * ATT_STRIDE + nb * 16 + asel) * 2);
        #pragma unroll
        for (int mi = 0; mi < 2; mi++)
            #pragma unroll
            for (int nt = 0; nt < 4; nt++)
                mma_bf16(o[mi][nt][0], o[mi][nt][1], o[mi][nt][2], o[mi][nt][3],
                         pk[mi][2*kt][0], pk[mi][2*kt][1], pk[mi][2*kt+1][0], pk[mi][2*kt+1][1],
                         bv[nt][0], bv[nt][1]);
    }

    // head-blocked output
    __nv_bfloat16* ob = out + (((size_t)wnd * 8 + head) << 11);
    #pragma unroll
    for (int mi = 0; mi < 2; mi++)
        #pragma unroll
        for (int nt = 0; nt < 4; nt++)
            #pragma unroll
            for (int hh = 0; hh < 2; hh++) {
                int row = m0 + mi * 16 + hh * 8 + r0;
                int col = nt * 8 + cq;
                __nv_bfloat162 p = __floats2bfloat162_rn(o[mi][nt][hh * 2],
                                                         o[mi][nt][hh * 2 + 1]);
                *(__nv_bfloat162*)(ob + (row << 5) + col) = p;
            }
}

// ---------------------------------------------------------------------------
// bf16 tensor-core GEMM (R11 proven): 256 threads, 8 warps 4x2, warp tile 32x64,
// CTA 128x128, BK=64, 3-stage cp.async ring, warp-staggered ks order.
// EPI: 0 = bf16 out, 2 = GELU + bf16 out, 3 = +res fp32 out, 4 = head-blocked bf16 (qkv)
// ABLK: 0 = row-major A, 2 = 32-col head-blocked A
#define SA_STRIDE 72
#define SB_STRIDE 136
#define ASTAGE (128 * SA_STRIDE * 2)
#define BSTAGE (64 * SB_STRIDE * 2)
#define GEMM_SMEM (3 * (ASTAGE + BSTAGE))

template<int EPI, int KN, int ABLK = 0>
__global__ void __launch_bounds__(256, 2) k_mmagemm(
    const __nv_bfloat16* __restrict__ A, const __nv_bfloat16* __restrict__ Bw,
    const float* __restrict__ bias, void* __restrict__ Cout,
    int N, const float* __restrict__ res) {
    constexpr int K = KN;
    constexpr int NIT = K >> 6;
    int tid  = threadIdx.x;
    int lane = tid & 31, warp = tid >> 5;
    int wy = warp >> 1, wx = warp & 1;
    int rowBase = blockIdx.y * 128;
    int colBase = blockIdx.x * 128;

    uint32_t sbase = (uint32_t)__cvta_generic_to_shared(dyn_smem);
    uint32_t sAs[3], sBs[3];
    #pragma unroll
    for (int s = 0; s < 3; s++) {
        sAs[s] = sbase + s * (ASTAGE + BSTAGE);
        sBs[s] = sAs[s] + ASTAGE;
    }

    auto issue = [&](int it) {
        int slot = it % 3;
        int k0 = it << 6;
        uint32_t sAu = sAs[slot], sBu = sBs[slot];
        #pragma unroll
        for (int i = 0; i < 4; i++) {
            int ch = tid + i * 256;
            int ar = ch >> 3, ac = ch & 7;
            const __nv_bfloat16* Ap;
            if (ABLK == 2) {
                int row = rowBase + ar;
                int k = k0 + ac * 8;
                Ap = A + (((size_t)(row >> 6) * (K >> 5) + (k >> 5)) << 11)
                       + ((row & 63) << 5) + (k & 31);
            } else {
                Ap = A + (size_t)(rowBase + ar) * K + k0 + ac * 8;
            }
            cp16(sAu + (uint32_t)(ar * SA_STRIDE + ac * 8) * 2, Ap);
            int bk = ch >> 4, bn = (ch & 15) * 8;
            cp16(sBu + (uint32_t)(bk * SB_STRIDE + bn) * 2,
                 Bw + (size_t)(k0 + bk) * N + colBase + bn);
        }
        asm volatile("cp.async.commit_group;\n" ::: "memory");
    };

    issue(0);
    if (NIT > 1) issue(1);

    float acc[2][8][4];
    #pragma unroll
    for (int i = 0; i < 2; i++)
        #pragma unroll
        for (int j = 0; j < 8; j++)
            #pragma unroll
            for (int t = 0; t < 4; t++) acc[i][j][t] = 0.f;

    int m0  = wy * 32;
    int n0w = wx * 64;
    int arow = lane & 15;
    int asel = (lane >> 4) << 3;
    int ksrot = warp & 3;

    for (int it = 0; it < NIT; it++) {
        if (it + 1 < NIT) asm volatile("cp.async.wait_group 1;\n" ::: "memory");
        else              asm volatile("cp.async.wait_group 0;\n" ::: "memory");
        __syncthreads();
        if (it + 2 < NIT) issue(it + 2);

        int slot = it % 3;
        uint32_t sAu = sAs[slot], sBu = sBs[slot];

        #pragma unroll
        for (int ksi = 0; ksi < 4; ksi++) {
            int ks = (ksi + ksrot) & 3;
            int k0 = ks * 16;
            uint32_t a[2][4];
            #pragma unroll
            for (int mi = 0; mi < 2; mi++)
                ldsm_x4(a[mi][0], a[mi][1], a[mi][2], a[mi][3],
                        sAu + (uint32_t)((m0 + mi * 16 + arow) * SA_STRIDE + k0 + asel) * 2);
            uint32_t b[8][2];
            #pragma unroll
            for (int nj = 0; nj < 4; nj++)
                ldsm_x4t(b[2 * nj][0], b[2 * nj][1], b[2 * nj + 1][0], b[2 * nj + 1][1],
                         sBu + (uint32_t)((k0 + (lane & 15)) * SB_STRIDE
                                          + n0w + nj * 16 + ((lane >> 4) << 3)) * 2);
            #pragma unroll
            for (int mi = 0; mi < 2; mi++)
                #pragma unroll
                for (int ni = 0; ni < 8; ni++)
                    mma_bf16(acc[mi][ni][0], acc[mi][ni][1], acc[mi][ni][2], acc[mi][ni][3],
                             a[mi][0], a[mi][1], a[mi][2], a[mi][3], b[ni][0], b[ni][1]);
        }
    }

    int gr = lane >> 2, gc = (lane & 3) * 2;
    float bias_r[8][2];
    #pragma unroll
    for (int ni = 0; ni < 8; ni++) {
        int col = colBase + n0w + ni * 8 + gc;
        bias_r[ni][0] = bias[col];
        bias_r[ni][1] = bias[col + 1];
    }
    #pragma unroll
    for (int mi = 0; mi < 2; mi++) {
        #pragma unroll
        for (int ni = 0; ni < 8; ni++) {
            int col = colBase + n0w + ni * 8 + gc;
            #pragma unroll
            for (int half = 0; half < 2; half++) {
                size_t row = (size_t)(rowBase + m0 + mi * 16 + gr + half * 8);
                float v0 = acc[mi][ni][half * 2 + 0] + bias_r[ni][0];
                float v1 = acc[mi][ni][half * 2 + 1] + bias_r[ni][1];
                if (EPI == 2) {
                    v0 = 0.5f * v0 * (1.0f + erff(v0 * 0.70710678118654752f));
                    v1 = 0.5f * v1 * (1.0f + erff(v1 * 0.70710678118654752f));
                }
                if (EPI == 3) {
                    v0 += res[row * N + col];
                    v1 += res[row * N + col + 1];
                    float2* p = (float2*)((float*)Cout + row * N + col);
                    *p = make_float2(v0, v1);
                } else if (EPI == 4) {
                    size_t addr = ((((row >> 6) * 24) + (size_t)(col >> 5)) << 11)
                                  + ((row & 63) << 5) + (col & 31);
                    *(__nv_bfloat162*)((__nv_bfloat16*)Cout + addr) =
                        __floats2bfloat162_rn(v0, v1);
                } else {
                    __nv_bfloat162* p = (__nv_bfloat162*)((__nv_bfloat16*)Cout + row * N + col);
                    *p = __floats2bfloat162_rn(v0, v1);
                }
            }
        }
    }
}

// ---------------------------------------------------------------------------
extern "C" void kernel_launch(void* const* d_in, const int* in_sizes, int n_in,
                              void* d_out, int out_size) {
    const float* x      = (const float*)d_in[0];
    const float* n1g    = (const float*)d_in[1];
    const float* n1b    = (const float*)d_in[2];
    const float* qkv_w  = (const float*)d_in[3];
    const float* qkv_b  = (const float*)d_in[4];
    const float* proj_w = (const float*)d_in[5];
    const float* proj_b = (const float*)d_in[6];
    const float* rpb    = (const float*)d_in[7];
    const float* n2g    = (const float*)d_in[8];
    const float* n2b    = (const float*)d_in[9];
    const float* fc1_w  = (const float*)d_in[10];
    const float* fc1_b  = (const float*)d_in[11];
    const float* fc2_w  = (const float*)d_in[12];
    const float* fc2_b  = (const float*)d_in[13];
    float* out = (float*)d_out;

    __nv_bfloat16 *ln, *big, *attn, *wts;
    float *x1, *btab;
    cudaGetSymbolAddress((void**)&ln,   g_ln);
    cudaGetSymbolAddress((void**)&big,  g_big);
    cudaGetSymbolAddress((void**)&attn, g_attn);
    cudaGetSymbolAddress((void**)&x1,   g_x1);
    cudaGetSymbolAddress((void**)&wts,  g_w);
    cudaGetSymbolAddress((void**)&btab, g_btab);

    cudaFuncSetAttribute(k_attn_mma, cudaFuncAttributeMaxDynamicSharedMemorySize, ATT_SMEM);
    cudaFuncSetAttribute((const void*)k_mmagemm<4, 256>,     cudaFuncAttributeMaxDynamicSharedMemorySize, GEMM_SMEM);
    cudaFuncSetAttribute((const void*)k_mmagemm<0, 256, 2>,  cudaFuncAttributeMaxDynamicSharedMemorySize, GEMM_SMEM);
    cudaFuncSetAttribute((const void*)k_mmagemm<2, 256>,     cudaFuncAttributeMaxDynamicSharedMemorySize, GEMM_SMEM);
    cudaFuncSetAttribute((const void*)k_mmagemm<3, 1024>,    cudaFuncAttributeMaxDynamicSharedMemorySize, GEMM_SMEM);

    // 0) merged prologue: weights -> bf16, bias+mask table
    k_pre<<<3136, 256>>>(qkv_w, proj_w, fc1_w, fc2_w, wts, rpb, btab);

    // 1) LN1 + roll + window partition -> ln
    k_ln1_v2<<<Tv / 8, 256>>>(x, n1g, n1b, ln);
    // 2) qkv GEMM: ln -> big (head-blocked layout)
    k_mmagemm<4, 256><<<dim3(768 / 128, Tv / 128), 256, GEMM_SMEM>>>(ln, wts + WOFF_QKV, qkv_b, big, 768, nullptr);
    // 3) attention (1 head/block, 8 CTAs/SM): big -> attn (head-blocked)
    k_attn_mma<<<BWIN * 8, 64, ATT_SMEM>>>(big, btab, attn);
    // 4) proj GEMM: attn (blocked A) -> ln (bf16)
    k_mmagemm<0, 256, 2><<<dim3(256 / 128, Tv / 128), 256, GEMM_SMEM>>>(attn, wts + WOFF_PROJ, proj_b, ln, 256, nullptr);
    // 5) x1 = x + reverse(roll(ln)); LN2 -> x1 (fp32), attn (bf16, natural)
    k_x1_ln2_v2<<<Tv / 8, 256>>>(x, ln, n2g, n2b, x1, attn);
    // 6) fc1 + GELU: attn -> big
    k_mmagemm<2, 256><<<dim3(1024 / 128, Tv / 128), 256, GEMM_SMEM>>>(attn, wts + WOFF_FC1, fc1_b, big, 1024, nullptr);
    // 7) fc2 + residual(x1): big -> out
    k_mmagemm<3, 1024><<<dim3(256 / 128, Tv / 128), 256, GEMM_SMEM>>>(big, wts + WOFF_FC2, fc2_b, out, 256, x1);
}